// round 10
// baseline (speedup 1.0000x reference)
#include <cuda_runtime.h>
#include <cuda_fp16.h>

#define NQ      10000
#define D       128
#define NHEADS  8
#define NPOINTS 4
#define HSP     51
#define WSP     102
#define HW      (HSP * WSP)
#define NL      50
#define HD      16
#define TPB     256
#define GRID    592

// Scratch (device globals; no allocation allowed).
__device__ __align__(128) __half g_projh[NHEADS * HW * HD];  // fp16 table 1.33MB
__device__ float g_G[NHEADS * HW];    // fp32 scalar field, row-major [h][y*W+x]
__device__ unsigned g_arrive = 0;
__device__ unsigned g_depart = 0;

// ---------------------------------------------------------------------------
__global__ void __launch_bounds__(TPB, 4)
fused_kernel(const float* __restrict__ query,
             const float* __restrict__ value,
             const float* __restrict__ ref,
             const float* __restrict__ W_off,
             const float* __restrict__ b_off,
             const float* __restrict__ W_attn,
             const float* __restrict__ b_attn,
             const float* __restrict__ W_val,
             const float* __restrict__ b_val,
             const float* __restrict__ W_out,
             const float* __restrict__ b_out,
             const float* __restrict__ W_proj,
             float* __restrict__ out,
             float* __restrict__ out_idx,
             int n_idx,
             float* __restrict__ tailp,
             int tail_n) {
    __shared__ float s_msda[NL * D];      // 25.6 KB
    __shared__ float s_q[D];
    __shared__ float s_avg[D];
    __shared__ float s_off[64];           // pre-normalized offsets (x,y per h,p)
    __shared__ float s_aw[32];            // point softmax weights
    __shared__ float s_wp[D];             // W_out @ W_proj
    __shared__ float s_wts[64];           // level weights
    __shared__ float s_refy[NL];
    __shared__ float s_refx;
    __shared__ float s_part[D];
    __shared__ float s_wx[64];            // masked x-corner weights per (h,p)
    __shared__ int   s_cx[64];            // clamped x-corner coords per (h,p)
    __shared__ float s_lg[NL];            // full fp32 level logits
    __shared__ float s_val[2 * D];        // phase-0 staging

    const __half* __restrict__ proj = g_projh;
    int tid = threadIdx.x;

    // ===================== wp = W_out @ W_proj (needed in phase 0) ==========
    {
        if (tid < D) s_avg[tid] = W_proj[tid];
        __syncthreads();
        int warp = tid >> 5, lane = tid & 31;
        for (int r = warp; r < D; r += 8) {
            float a = 0.f;
#pragma unroll
            for (int kk = 0; kk < 4; kk++) {
                int k = lane + kk * 32;
                a = fmaf(W_out[r * D + k], s_avg[k], a);
            }
#pragma unroll
            for (int o = 16; o; o >>= 1)
                a += __shfl_down_sync(0xffffffffu, a, o);
            if (lane == 0) s_wp[r] = a;
        }
        __syncthreads();
    }

    // ===================== phase 0: value projection (fp32->fp16 + G) =======
    {
        int ch = tid & 127;
        int half_ = tid >> 7;
        float wpc = s_wp[ch];
        for (int s0 = blockIdx.x * 2; s0 < HW; s0 += GRID * 2) {
            int s = s0 + half_;
            bool ok = s < HW;
            __syncthreads();
            if (ok) s_val[half_ * D + ch] = value[s * D + ch];
            __syncthreads();
            float acc = 0.f;
            if (ok) {
                acc = b_val[ch];
                const float* vr = &s_val[half_ * D];
#pragma unroll 8
                for (int k = 0; k < D; k++)
                    acc = fmaf(vr[k], W_val[k * D + ch], acc);
                g_projh[(ch >> 4) * (HW * HD) + s * HD + (ch & 15)] =
                    __float2half(acc);
            }
            // fp32 scalar field G[h][s] = sum_c proj_fp32 * wp (16-lane reduce)
            float gterm = acc * wpc;
#pragma unroll
            for (int o = 1; o < 16; o <<= 1)
                gterm += __shfl_xor_sync(0xffffffffu, gterm, o);
            if (ok && (tid & 15) == 0)
                g_G[(ch >> 4) * HW + s] = gterm;
        }
        for (int i = blockIdx.x * TPB + tid; i < tail_n; i += GRID * TPB)
            tailp[i] = 0.f;
    }

    // ===================== device-wide barrier ==============================
    __syncthreads();
    if (tid == 0) {
        __threadfence();
        atomicAdd(&g_arrive, 1u);
        while (*(volatile unsigned*)&g_arrive < GRID) { }
        __threadfence();
        unsigned old = atomicAdd(&g_depart, 1u);
        if (old == GRID - 1) {
            *(volatile unsigned*)&g_arrive = 0u;
            __threadfence();
            *(volatile unsigned*)&g_depart = 0u;
        }
    }
    __syncthreads();

    // ===================== phase 1: per-query attention =====================
    for (int q = blockIdx.x; q < NQ; q += GRID) {
        __syncthreads();
        if (tid < D) s_q[tid] = query[q * D + tid];
        __syncthreads();

        // ---- offsets (64) + attn logits (32): 192-thread k-split GEMV;
        //      warps 6-7 load ref y per level (+ the z-invariant x)
        if (tid < 192) {
            int col = tid >> 1;
            int half_ = tid & 1;
            bool is_off = col < 64;
            const float* W = is_off ? (W_off + col) : (W_attn + (col - 64));
            int stride = is_off ? 64 : 32;
            float acc = 0.f;
            if (half_ == 0)
                acc = is_off ? b_off[col] : b_attn[col - 64];
            int k0 = half_ * 64;
#pragma unroll 8
            for (int k = 0; k < 64; k++)
                acc = fmaf(s_q[k0 + k], W[(k0 + k) * stride], acc);
            acc += __shfl_xor_sync(0xffffffffu, acc, 1);
            if (half_ == 0) {
                if (is_off)
                    s_off[col] = acc / ((col & 1) ? (float)HSP : (float)WSP);
                else
                    s_aw[col - 64] = acc;
            }
        } else {
            int i = tid - 192;
            if (i < NL)
                s_refy[i] = ref[i * (NQ * 2) + q * 2 + 1];
            else if (i == NL)
                s_refx = ref[q * 2 + 0];
        }
        __syncthreads();

        // ---- point softmax (tid<8) + per-(h,p) x precompute (tid 32..63)
        if (tid < NHEADS) {
            float m = s_aw[tid * 4];
#pragma unroll
            for (int p = 1; p < 4; p++) m = fmaxf(m, s_aw[tid * 4 + p]);
            float e[4]; float ssum = 0.f;
#pragma unroll
            for (int p = 0; p < 4; p++) {
                e[p] = expf(s_aw[tid * 4 + p] - m);
                ssum += e[p];
            }
            float inv = 1.f / ssum;
#pragma unroll
            for (int p = 0; p < 4; p++) s_aw[tid * 4 + p] = e[p] * inv;
        } else if (tid >= 32 && tid < 64) {
            int up = tid - 32;
            float px = (s_refx + s_off[up * 2]) * (float)WSP - 0.5f;
            float x0f = floorf(px);
            float dx = px - x0f;
            int x0 = (int)x0f;
            s_wx[up * 2 + 0] = ((unsigned)x0 < WSP) ? (1.f - dx) : 0.f;
            s_wx[up * 2 + 1] = ((unsigned)(x0 + 1) < WSP) ? dx : 0.f;
            s_cx[up * 2 + 0] = min(max(x0, 0), WSP - 1);
            s_cx[up * 2 + 1] = min(max(x0 + 1, 0), WSP - 1);
        }
        __syncthreads();

        // ---- MSDA channel sampling (fp16): unit = (level, head), 4 lanes.
        //      lane bits: bit1 = x-corner, bit0 = chan octet. For a fixed
        //      slot, h is loop-invariant -> per-head terms hoisted.
        //      Fast path: all 4 points share x-corner AND y0-span<=1 ->
        //      fold point weights (fp32, exact at equal addresses) and load
        //      a shared 2-3 row window instead of 8 per-point rows.
        {
            int j = tid & 3;
            int slot = tid >> 2;             // 0..63
            int xc = j >> 1;
            int co = (j & 1) * 8;            // channel octet offset (halves)
            int h = slot & 7;                // invariant across iterations
            const __half* basep = proj + h * (HW * HD) + co;

            float wxaw[4], offy[4];
            int cxl[4];
#pragma unroll
            for (int p = 0; p < 4; p++) {
                int up = h * 4 + p;
                wxaw[p] = s_wx[up * 2 + xc] * s_aw[up];
                offy[p] = s_off[up * 2 + 1];
                cxl[p]  = s_cx[up * 2 + xc];
            }
            bool xuni = (cxl[0] == cxl[1]) && (cxl[0] == cxl[2]) &&
                        (cxl[0] == cxl[3]);

            for (int u = slot; u < NL * NHEADS; u += 64) {
                int l = u >> 3;
                float ry = s_refy[l];
                float dy_[4]; int y0_[4];
#pragma unroll
                for (int p = 0; p < 4; p++) {
                    float py = (ry + offy[p]) * (float)HSP - 0.5f;
                    float y0f = floorf(py);
                    y0_[p] = (int)y0f;
                    dy_[p] = py - y0f;
                }
                int ylo = min(min(y0_[0], y0_[1]), min(y0_[2], y0_[3]));
                int yhi = max(max(y0_[0], y0_[1]), max(y0_[2], y0_[3]));
                __half2 ac0 = __float2half2_rn(0.f);
                __half2 ac1 = ac0, ac2 = ac0, ac3 = ac0;

                if (xuni && (yhi - ylo) <= 1) {
                    float w0 = 0.f, w1 = 0.f, w2 = 0.f;
#pragma unroll
                    for (int p = 0; p < 4; p++) {
                        bool dz = (y0_[p] == ylo);
                        float a = (1.f - dy_[p]) * wxaw[p];
                        float b = dy_[p] * wxaw[p];
                        w0 += dz ? a : 0.f;
                        w1 += dz ? b : a;
                        w2 += dz ? 0.f : b;
                    }
                    w0 *= ((unsigned)ylo < HSP) ? 1.f : 0.f;
                    w1 *= ((unsigned)(ylo + 1) < HSP) ? 1.f : 0.f;
                    w2 *= ((unsigned)(ylo + 2) < HSP) ? 1.f : 0.f;
                    int cy0 = min(max(ylo, 0), HSP - 1);
                    int cy1 = min(max(ylo + 1, 0), HSP - 1);
                    int xb = cxl[0];
                    uint4 v0 = *(const uint4*)(basep + (cy0 * WSP + xb) * HD);
                    uint4 v1 = *(const uint4*)(basep + (cy1 * WSP + xb) * HD);
                    __half2 hw0 = __float2half2_rn(w0);
                    __half2 hw1 = __float2half2_rn(w1);
                    ac0 = __hfma2(*(__half2*)&v0.x, hw0, ac0);
                    ac1 = __hfma2(*(__half2*)&v0.y, hw0, ac1);
                    ac2 = __hfma2(*(__half2*)&v0.z, hw0, ac2);
                    ac3 = __hfma2(*(__half2*)&v0.w, hw0, ac3);
                    ac0 = __hfma2(*(__half2*)&v1.x, hw1, ac0);
                    ac1 = __hfma2(*(__half2*)&v1.y, hw1, ac1);
                    ac2 = __hfma2(*(__half2*)&v1.z, hw1, ac2);
                    ac3 = __hfma2(*(__half2*)&v1.w, hw1, ac3);
                    if (yhi != ylo) {            // third row only when span==1
                        int cy2 = min(max(ylo + 2, 0), HSP - 1);
                        uint4 v2 = *(const uint4*)(basep + (cy2 * WSP + xb) * HD);
                        __half2 hw2 = __float2half2_rn(w2);
                        ac0 = __hfma2(*(__half2*)&v2.x, hw2, ac0);
                        ac1 = __hfma2(*(__half2*)&v2.y, hw2, ac1);
                        ac2 = __hfma2(*(__half2*)&v2.z, hw2, ac2);
                        ac3 = __hfma2(*(__half2*)&v2.w, hw2, ac3);
                    }
                } else {
                    // exact per-point fallback (identical math to R9)
#pragma unroll
                    for (int p = 0; p < NPOINTS; p++) {
                        float dy = dy_[p];
                        int y0 = y0_[p];
                        float wy0 = ((unsigned)y0 < HSP) ? (1.f - dy) : 0.f;
                        float wy1 = ((unsigned)(y0 + 1) < HSP) ? dy : 0.f;
                        int cy0 = min(max(y0, 0), HSP - 1);
                        int cy1 = min(max(y0 + 1, 0), HSP - 1);
                        int xcoord = cxl[p];
                        uint4 v0 = *(const uint4*)(basep + (cy0 * WSP + xcoord) * HD);
                        uint4 v1 = *(const uint4*)(basep + (cy1 * WSP + xcoord) * HD);
                        __half2 w0 = __float2half2_rn(wxaw[p] * wy0);
                        __half2 w1 = __float2half2_rn(wxaw[p] * wy1);
                        ac0 = __hfma2(*(__half2*)&v0.x, w0, ac0);
                        ac1 = __hfma2(*(__half2*)&v0.y, w0, ac1);
                        ac2 = __hfma2(*(__half2*)&v0.z, w0, ac2);
                        ac3 = __hfma2(*(__half2*)&v0.w, w0, ac3);
                        ac0 = __hfma2(*(__half2*)&v1.x, w1, ac0);
                        ac1 = __hfma2(*(__half2*)&v1.y, w1, ac1);
                        ac2 = __hfma2(*(__half2*)&v1.z, w1, ac2);
                        ac3 = __hfma2(*(__half2*)&v1.w, w1, ac3);
                    }
                }
                // combine x-corner halves (lanes j and j^2)
                unsigned t;
                t = __shfl_xor_sync(0xffffffffu, *(unsigned*)&ac0, 2);
                ac0 = __hadd2(ac0, *(__half2*)&t);
                t = __shfl_xor_sync(0xffffffffu, *(unsigned*)&ac1, 2);
                ac1 = __hadd2(ac1, *(__half2*)&t);
                t = __shfl_xor_sync(0xffffffffu, *(unsigned*)&ac2, 2);
                ac2 = __hadd2(ac2, *(__half2*)&t);
                t = __shfl_xor_sync(0xffffffffu, *(unsigned*)&ac3, 2);
                ac3 = __hadd2(ac3, *(__half2*)&t);
                if (j < 2) {
                    float2 f0 = __half22float2(ac0);
                    float2 f1 = __half22float2(ac1);
                    float2 f2 = __half22float2(ac2);
                    float2 f3 = __half22float2(ac3);
                    int db = l * D + h * HD + co;
                    float4 w_;
                    w_.x = f0.x; w_.y = f0.y; w_.z = f1.x; w_.w = f1.y;
                    *(float4*)&s_msda[db] = w_;
                    float4 w2_;
                    w2_.x = f2.x; w2_.y = f2.y; w2_.z = f3.x; w2_.w = f3.y;
                    *(float4*)&s_msda[db + 4] = w2_;
                }
            }

            // ---- exact fp32 level logits: warp = level, lane = (h,p).
            int warp = tid >> 5;
            int lane = tid & 31;             // lane == up == h*4+p
            int hh = lane >> 2;
            const float* Gh = g_G + hh * HW;
            float wx0 = s_wx[lane * 2 + 0];
            float wx1 = s_wx[lane * 2 + 1];
            int cx0 = s_cx[lane * 2 + 0];
            int cx1 = s_cx[lane * 2 + 1];
            float goffy = s_off[lane * 2 + 1];
            float awl = s_aw[lane];
            for (int l = warp; l < NL; l += 8) {
                float py = (s_refy[l] + goffy) * (float)HSP - 0.5f;
                float y0f = floorf(py);
                float dy = py - y0f;
                int y0 = (int)y0f;
                float wy0 = ((unsigned)y0 < HSP) ? (1.f - dy) : 0.f;
                float wy1 = ((unsigned)(y0 + 1) < HSP) ? dy : 0.f;
                int cy0 = min(max(y0, 0), HSP - 1);
                int cy1 = min(max(y0 + 1, 0), HSP - 1);
                const float* r0 = Gh + cy0 * WSP;
                const float* r1 = Gh + cy1 * WSP;
                float g00 = r0[cx0], g01 = r0[cx1];
                float g10 = r1[cx0], g11 = r1[cx1];
                float t = awl * (wy0 * fmaf(wx0, g00, wx1 * g01)
                               + wy1 * fmaf(wx0, g10, wx1 * g11));
#pragma unroll
                for (int o = 16; o; o >>= 1)
                    t += __shfl_xor_sync(0xffffffffu, t, o);
                if (lane == 0) s_lg[l] = t;
            }
        }
        __syncthreads();

        // ---- level softmax + argmax: warp 0, parallel
        if (tid < 32) {
            float v0 = (tid < NL) ? s_lg[tid] : -3.4e38f;
            float v1 = (tid + 32 < NL) ? s_lg[tid + 32] : -3.4e38f;
            float bv; int bi;
            if (v1 > v0) { bv = v1; bi = tid + 32; }
            else         { bv = v0; bi = tid; }
#pragma unroll
            for (int o = 16; o; o >>= 1) {
                float ov = __shfl_down_sync(0xffffffffu, bv, o);
                int   oi = __shfl_down_sync(0xffffffffu, bi, o);
                if (ov > bv || (ov == bv && oi < bi)) { bv = ov; bi = oi; }
            }
            bv = __shfl_sync(0xffffffffu, bv, 0);
            float e0 = (tid < NL) ? expf(v0 - bv) : 0.f;
            float e1 = (tid + 32 < NL) ? expf(v1 - bv) : 0.f;
            float ssum = e0 + e1;
#pragma unroll
            for (int o = 16; o; o >>= 1)
                ssum += __shfl_xor_sync(0xffffffffu, ssum, o);
            float inv = 1.f / ssum;
            if (tid < NL) s_wts[tid] = e0 * inv;
            if (tid + 32 < NL) s_wts[tid + 32] = e1 * inv;
            if (tid == 0 && q < n_idx) out_idx[q] = (float)bi;
        }
        __syncthreads();

        // ---- weighted average over levels
        if (tid < D) {
            float acc = 0.f;
#pragma unroll 5
            for (int l = 0; l < NL; l++)
                acc = fmaf(s_wts[l], s_msda[l * D + tid], acc);
            s_avg[tid] = acc;
        }
        __syncthreads();

        // ---- final: out = avg @ W_out + b_out + 2*query  (k-split, 256 thr)
        {
            int ch = tid & 127, half_ = tid >> 7;
            int k0 = half_ * 64;
            float acc = 0.f;
#pragma unroll 8
            for (int k = 0; k < 64; k++)
                acc = fmaf(s_avg[k0 + k], W_out[(k0 + k) * D + ch], acc);
            if (half_) s_part[ch] = acc;
            __syncthreads();
            if (!half_)
                out[q * D + ch] = acc + s_part[ch] + b_out[ch] + 2.0f * s_q[ch];
        }
    }
}

// ---------------------------------------------------------------------------
extern "C" void kernel_launch(void* const* d_in, const int* in_sizes, int n_in,
                              void* d_out, int out_size) {
    const float* query  = (const float*)d_in[0];
    const float* value  = (const float*)d_in[1];
    const float* refp   = (const float*)d_in[2];
    const float* W_off  = (const float*)d_in[3];
    const float* b_off  = (const float*)d_in[4];
    const float* W_attn = (const float*)d_in[5];
    const float* b_attn = (const float*)d_in[6];
    const float* W_val  = (const float*)d_in[7];
    const float* b_val  = (const float*)d_in[8];
    const float* W_out  = (const float*)d_in[9];
    const float* b_out  = (const float*)d_in[10];
    const float* W_proj = (const float*)d_in[11];
    // b_proj (d_in[12]) unused: constant shift is softmax/argmax-invariant.

    float* out = (float*)d_out;

    int n_idx = out_size - NQ * D;
    if (n_idx < 0) n_idx = 0;
    if (n_idx > NQ) n_idx = NQ;

    int tail_n = out_size - (NQ * D + NQ);
    float* tailp = out + NQ * D + NQ;
    if (tail_n < 0) { tail_n = 0; tailp = out; }

    fused_kernel<<<GRID, TPB>>>(query, value, refp, W_off, b_off,
                                W_attn, b_attn, W_val, b_val,
                                W_out, b_out, W_proj,
                                out, out + NQ * D, n_idx, tailp, tail_n);
}

// round 11
// speedup vs baseline: 1.0189x; 1.0189x over previous
#include <cuda_runtime.h>
#include <cuda_fp16.h>

#define NQ      10000
#define D       128
#define NHEADS  8
#define NPOINTS 4
#define HSP     51
#define WSP     102
#define HW      (HSP * WSP)
#define NL      50
#define HD      16
#define TPB     256
#define GRID    592

// Scratch (device globals; no allocation allowed).
// SPATIAL-MAJOR layouts: one grid cell holds all heads contiguously, so a
// warp (one level, 8 heads, near-identical sample coords) touches ~2 lines
// per gather instruction instead of ~10.
__device__ __align__(128) __half g_projh[HW * D];   // [s][h*16+c], 256B/cell
__device__ __align__(128) float  g_G[HW * NHEADS];  // [s][h], 32B/cell
__device__ unsigned g_arrive = 0;
__device__ unsigned g_depart = 0;

// ---------------------------------------------------------------------------
__global__ void __launch_bounds__(TPB, 4)
fused_kernel(const float* __restrict__ query,
             const float* __restrict__ value,
             const float* __restrict__ ref,
             const float* __restrict__ W_off,
             const float* __restrict__ b_off,
             const float* __restrict__ W_attn,
             const float* __restrict__ b_attn,
             const float* __restrict__ W_val,
             const float* __restrict__ b_val,
             const float* __restrict__ W_out,
             const float* __restrict__ b_out,
             const float* __restrict__ W_proj,
             float* __restrict__ out,
             float* __restrict__ out_idx,
             int n_idx,
             float* __restrict__ tailp,
             int tail_n) {
    __shared__ float s_msda[NL * D];      // 25.6 KB
    __shared__ float s_q[D];
    __shared__ float s_avg[D];
    __shared__ float s_off[64];           // pre-normalized offsets (x,y per h,p)
    __shared__ float s_aw[32];            // point softmax weights
    __shared__ float s_wp[D];             // W_out @ W_proj
    __shared__ float s_wts[64];           // level weights
    __shared__ float s_refy[NL];
    __shared__ float s_refx;
    __shared__ float s_part[D];
    __shared__ float s_wx[64];            // masked x-corner weights per (h,p)
    __shared__ int   s_cx[64];            // clamped x-corner coords per (h,p)
    __shared__ float s_lg[NL];            // full fp32 level logits
    __shared__ float s_val[2 * D];        // phase-0 staging

    const __half* __restrict__ proj = g_projh;
    int tid = threadIdx.x;

    // ===================== wp = W_out @ W_proj (needed in phase 0) ==========
    {
        if (tid < D) s_avg[tid] = W_proj[tid];
        __syncthreads();
        int warp = tid >> 5, lane = tid & 31;
        for (int r = warp; r < D; r += 8) {
            float a = 0.f;
#pragma unroll
            for (int kk = 0; kk < 4; kk++) {
                int k = lane + kk * 32;
                a = fmaf(W_out[r * D + k], s_avg[k], a);
            }
#pragma unroll
            for (int o = 16; o; o >>= 1)
                a += __shfl_down_sync(0xffffffffu, a, o);
            if (lane == 0) s_wp[r] = a;
        }
        __syncthreads();
    }

    // ===================== phase 0: value projection (fp32->fp16 + G) =======
    {
        int ch = tid & 127;
        int half_ = tid >> 7;
        float wpc = s_wp[ch];
        for (int s0 = blockIdx.x * 2; s0 < HW; s0 += GRID * 2) {
            int s = s0 + half_;
            bool ok = s < HW;
            __syncthreads();
            if (ok) s_val[half_ * D + ch] = value[s * D + ch];
            __syncthreads();
            float acc = 0.f;
            if (ok) {
                acc = b_val[ch];
                const float* vr = &s_val[half_ * D];
#pragma unroll 8
                for (int k = 0; k < D; k++)
                    acc = fmaf(vr[k], W_val[k * D + ch], acc);
                g_projh[s * D + ch] = __float2half(acc);   // spatial-major
            }
            // fp32 scalar field G[s][h] = sum_c proj_fp32 * wp (16-lane reduce)
            float gterm = acc * wpc;
#pragma unroll
            for (int o = 1; o < 16; o <<= 1)
                gterm += __shfl_xor_sync(0xffffffffu, gterm, o);
            if (ok && (tid & 15) == 0)
                g_G[s * NHEADS + (ch >> 4)] = gterm;       // spatial-major
        }
        for (int i = blockIdx.x * TPB + tid; i < tail_n; i += GRID * TPB)
            tailp[i] = 0.f;
    }

    // ===================== device-wide barrier ==============================
    __syncthreads();
    if (tid == 0) {
        __threadfence();
        atomicAdd(&g_arrive, 1u);
        while (*(volatile unsigned*)&g_arrive < GRID) { }
        __threadfence();
        unsigned old = atomicAdd(&g_depart, 1u);
        if (old == GRID - 1) {
            *(volatile unsigned*)&g_arrive = 0u;
            __threadfence();
            *(volatile unsigned*)&g_depart = 0u;
        }
    }
    __syncthreads();

    // ===================== phase 1: per-query attention =====================
    for (int q = blockIdx.x; q < NQ; q += GRID) {
        __syncthreads();
        if (tid < D) s_q[tid] = query[q * D + tid];
        __syncthreads();

        // ---- offsets (64) + attn logits (32): 192-thread k-split GEMV;
        //      warps 6-7 load ref y per level (+ the z-invariant x)
        if (tid < 192) {
            int col = tid >> 1;
            int half_ = tid & 1;
            bool is_off = col < 64;
            const float* W = is_off ? (W_off + col) : (W_attn + (col - 64));
            int stride = is_off ? 64 : 32;
            float acc = 0.f;
            if (half_ == 0)
                acc = is_off ? b_off[col] : b_attn[col - 64];
            int k0 = half_ * 64;
#pragma unroll 8
            for (int k = 0; k < 64; k++)
                acc = fmaf(s_q[k0 + k], W[(k0 + k) * stride], acc);
            acc += __shfl_xor_sync(0xffffffffu, acc, 1);
            if (half_ == 0) {
                if (is_off)
                    s_off[col] = acc / ((col & 1) ? (float)HSP : (float)WSP);
                else
                    s_aw[col - 64] = acc;
            }
        } else {
            int i = tid - 192;
            if (i < NL)
                s_refy[i] = ref[i * (NQ * 2) + q * 2 + 1];
            else if (i == NL)
                s_refx = ref[q * 2 + 0];
        }
        __syncthreads();

        // ---- point softmax (tid<8) + per-(h,p) x precompute (tid 32..63)
        if (tid < NHEADS) {
            float m = s_aw[tid * 4];
#pragma unroll
            for (int p = 1; p < 4; p++) m = fmaxf(m, s_aw[tid * 4 + p]);
            float e[4]; float ssum = 0.f;
#pragma unroll
            for (int p = 0; p < 4; p++) {
                e[p] = expf(s_aw[tid * 4 + p] - m);
                ssum += e[p];
            }
            float inv = 1.f / ssum;
#pragma unroll
            for (int p = 0; p < 4; p++) s_aw[tid * 4 + p] = e[p] * inv;
        } else if (tid >= 32 && tid < 64) {
            int up = tid - 32;
            float px = (s_refx + s_off[up * 2]) * (float)WSP - 0.5f;
            float x0f = floorf(px);
            float dx = px - x0f;
            int x0 = (int)x0f;
            s_wx[up * 2 + 0] = ((unsigned)x0 < WSP) ? (1.f - dx) : 0.f;
            s_wx[up * 2 + 1] = ((unsigned)(x0 + 1) < WSP) ? dx : 0.f;
            s_cx[up * 2 + 0] = min(max(x0, 0), WSP - 1);
            s_cx[up * 2 + 1] = min(max(x0 + 1, 0), WSP - 1);
        }
        __syncthreads();

        // ---- MSDA channel sampling (pure fp16): unit = (level, head),
        //      4 lanes per unit; lane bits: bit1 = x-corner, bit0 = chan octet.
        //      Spatial-major table: a warp's 8 heads hit ~the same cells.
        {
            int j = tid & 3;
            int slot = tid >> 2;             // 0..63
            int xc = j >> 1;
            int co = (j & 1) * 8;            // channel octet offset (halves)
            for (int u = slot; u < NL * NHEADS; u += 64) {
                int l = u >> 3, h = u & 7;
                float ry = s_refy[l];
                const __half* basep = proj + h * HD + co;
                __half2 ac0 = __float2half2_rn(0.f);
                __half2 ac1 = ac0, ac2 = ac0, ac3 = ac0;
#pragma unroll
                for (int p = 0; p < NPOINTS; p++) {
                    int up = h * 4 + p;
                    float py = (ry + s_off[up * 2 + 1]) * (float)HSP - 0.5f;
                    float y0f = floorf(py);
                    float dy = py - y0f;
                    int y0 = (int)y0f;
                    float wy0 = ((unsigned)y0 < HSP) ? (1.f - dy) : 0.f;
                    float wy1 = ((unsigned)(y0 + 1) < HSP) ? dy : 0.f;
                    int cy0 = min(max(y0, 0), HSP - 1);
                    int cy1 = min(max(y0 + 1, 0), HSP - 1);
                    float waw = s_wx[up * 2 + xc] * s_aw[up];
                    int xcoord = s_cx[up * 2 + xc];
                    const uint4* r0 = (const uint4*)(basep + (cy0 * WSP + xcoord) * D);
                    const uint4* r1 = (const uint4*)(basep + (cy1 * WSP + xcoord) * D);
                    uint4 v0 = *r0;
                    uint4 v1 = *r1;
                    __half2 w0 = __float2half2_rn(waw * wy0);
                    __half2 w1 = __float2half2_rn(waw * wy1);
                    ac0 = __hfma2(*(__half2*)&v0.x, w0, ac0);
                    ac1 = __hfma2(*(__half2*)&v0.y, w0, ac1);
                    ac2 = __hfma2(*(__half2*)&v0.z, w0, ac2);
                    ac3 = __hfma2(*(__half2*)&v0.w, w0, ac3);
                    ac0 = __hfma2(*(__half2*)&v1.x, w1, ac0);
                    ac1 = __hfma2(*(__half2*)&v1.y, w1, ac1);
                    ac2 = __hfma2(*(__half2*)&v1.z, w1, ac2);
                    ac3 = __hfma2(*(__half2*)&v1.w, w1, ac3);
                }
                // combine x-corner halves (lanes j and j^2)
                unsigned t;
                t = __shfl_xor_sync(0xffffffffu, *(unsigned*)&ac0, 2);
                ac0 = __hadd2(ac0, *(__half2*)&t);
                t = __shfl_xor_sync(0xffffffffu, *(unsigned*)&ac1, 2);
                ac1 = __hadd2(ac1, *(__half2*)&t);
                t = __shfl_xor_sync(0xffffffffu, *(unsigned*)&ac2, 2);
                ac2 = __hadd2(ac2, *(__half2*)&t);
                t = __shfl_xor_sync(0xffffffffu, *(unsigned*)&ac3, 2);
                ac3 = __hadd2(ac3, *(__half2*)&t);
                if (j < 2) {
                    float2 f0 = __half22float2(ac0);
                    float2 f1 = __half22float2(ac1);
                    float2 f2 = __half22float2(ac2);
                    float2 f3 = __half22float2(ac3);
                    int db = l * D + h * HD + co;
                    float4 w_;
                    w_.x = f0.x; w_.y = f0.y; w_.z = f1.x; w_.w = f1.y;
                    *(float4*)&s_msda[db] = w_;
                    float4 w2_;
                    w2_.x = f2.x; w2_.y = f2.y; w2_.z = f3.x; w2_.w = f3.y;
                    *(float4*)&s_msda[db + 4] = w2_;
                }
            }

            // ---- exact fp32 level logits: warp = level, lane = (h,p).
            //      Spatial-major G: a warp's 32 (h,p) lanes hit ~2-4 cells.
            int warp = tid >> 5;
            int lane = tid & 31;             // lane == up == h*4+p
            int hh = lane >> 2;
            float wx0 = s_wx[lane * 2 + 0];
            float wx1 = s_wx[lane * 2 + 1];
            int cx0 = s_cx[lane * 2 + 0];
            int cx1 = s_cx[lane * 2 + 1];
            float goffy = s_off[lane * 2 + 1];
            float awl = s_aw[lane];
            for (int l = warp; l < NL; l += 8) {
                float py = (s_refy[l] + goffy) * (float)HSP - 0.5f;
                float y0f = floorf(py);
                float dy = py - y0f;
                int y0 = (int)y0f;
                float wy0 = ((unsigned)y0 < HSP) ? (1.f - dy) : 0.f;
                float wy1 = ((unsigned)(y0 + 1) < HSP) ? dy : 0.f;
                int cy0 = min(max(y0, 0), HSP - 1);
                int cy1 = min(max(y0 + 1, 0), HSP - 1);
                const float* r0 = g_G + cy0 * (WSP * NHEADS) + hh;
                const float* r1 = g_G + cy1 * (WSP * NHEADS) + hh;
                float g00 = r0[cx0 * NHEADS], g01 = r0[cx1 * NHEADS];
                float g10 = r1[cx0 * NHEADS], g11 = r1[cx1 * NHEADS];
                float t = awl * (wy0 * fmaf(wx0, g00, wx1 * g01)
                               + wy1 * fmaf(wx0, g10, wx1 * g11));
#pragma unroll
                for (int o = 16; o; o >>= 1)
                    t += __shfl_xor_sync(0xffffffffu, t, o);
                if (lane == 0) s_lg[l] = t;
            }
        }
        __syncthreads();

        // ---- level softmax + argmax: warp 0, parallel
        if (tid < 32) {
            float v0 = (tid < NL) ? s_lg[tid] : -3.4e38f;
            float v1 = (tid + 32 < NL) ? s_lg[tid + 32] : -3.4e38f;
            float bv; int bi;
            if (v1 > v0) { bv = v1; bi = tid + 32; }
            else         { bv = v0; bi = tid; }
#pragma unroll
            for (int o = 16; o; o >>= 1) {
                float ov = __shfl_down_sync(0xffffffffu, bv, o);
                int   oi = __shfl_down_sync(0xffffffffu, bi, o);
                if (ov > bv || (ov == bv && oi < bi)) { bv = ov; bi = oi; }
            }
            bv = __shfl_sync(0xffffffffu, bv, 0);
            float e0 = (tid < NL) ? expf(v0 - bv) : 0.f;
            float e1 = (tid + 32 < NL) ? expf(v1 - bv) : 0.f;
            float ssum = e0 + e1;
#pragma unroll
            for (int o = 16; o; o >>= 1)
                ssum += __shfl_xor_sync(0xffffffffu, ssum, o);
            float inv = 1.f / ssum;
            if (tid < NL) s_wts[tid] = e0 * inv;
            if (tid + 32 < NL) s_wts[tid + 32] = e1 * inv;
            if (tid == 0 && q < n_idx) out_idx[q] = (float)bi;
        }
        __syncthreads();

        // ---- weighted average over levels
        if (tid < D) {
            float acc = 0.f;
#pragma unroll 5
            for (int l = 0; l < NL; l++)
                acc = fmaf(s_wts[l], s_msda[l * D + tid], acc);
            s_avg[tid] = acc;
        }
        __syncthreads();

        // ---- final: out = avg @ W_out + b_out + 2*query  (k-split, 256 thr)
        {
            int ch = tid & 127, half_ = tid >> 7;
            int k0 = half_ * 64;
            float acc = 0.f;
#pragma unroll 8
            for (int k = 0; k < 64; k++)
                acc = fmaf(s_avg[k0 + k], W_out[(k0 + k) * D + ch], acc);
            if (half_) s_part[ch] = acc;
            __syncthreads();
            if (!half_)
                out[q * D + ch] = acc + s_part[ch] + b_out[ch] + 2.0f * s_q[ch];
        }
    }
}

// ---------------------------------------------------------------------------
extern "C" void kernel_launch(void* const* d_in, const int* in_sizes, int n_in,
                              void* d_out, int out_size) {
    const float* query  = (const float*)d_in[0];
    const float* value  = (const float*)d_in[1];
    const float* refp   = (const float*)d_in[2];
    const float* W_off  = (const float*)d_in[3];
    const float* b_off  = (const float*)d_in[4];
    const float* W_attn = (const float*)d_in[5];
    const float* b_attn = (const float*)d_in[6];
    const float* W_val  = (const float*)d_in[7];
    const float* b_val  = (const float*)d_in[8];
    const float* W_out  = (const float*)d_in[9];
    const float* b_out  = (const float*)d_in[10];
    const float* W_proj = (const float*)d_in[11];
    // b_proj (d_in[12]) unused: constant shift is softmax/argmax-invariant.

    float* out = (float*)d_out;

    int n_idx = out_size - NQ * D;
    if (n_idx < 0) n_idx = 0;
    if (n_idx > NQ) n_idx = NQ;

    int tail_n = out_size - (NQ * D + NQ);
    float* tailp = out + NQ * D + NQ;
    if (tail_n < 0) { tail_n = 0; tailp = out; }

    fused_kernel<<<GRID, TPB>>>(query, value, refp, W_off, b_off,
                                W_attn, b_attn, W_val, b_val,
                                W_out, b_out, W_proj,
                                out, out + NQ * D, n_idx, tailp, tail_n);
}

// round 12
// speedup vs baseline: 1.2073x; 1.1849x over previous
#include <cuda_runtime.h>
#include <cuda_fp16.h>

#define NQ      10000
#define D       128
#define NHEADS  8
#define NPOINTS 4
#define HSP     51
#define WSP     102
#define HW      (HSP * WSP)
#define NL      50
#define HD      16
#define TPB     256
#define GRID    592

// Scratch (device globals; no allocation allowed). Head-major (best measured).
__device__ __align__(128) __half g_projh[NHEADS * HW * HD];  // fp16 1.33MB
__device__ float g_G[NHEADS * HW];    // fp32 scalar field [h][y*W+x]
__device__ unsigned g_arrive = 0;
__device__ unsigned g_depart = 0;

// ---------------------------------------------------------------------------
__global__ void __launch_bounds__(TPB, 4)
fused_kernel(const float* __restrict__ query,
             const float* __restrict__ value,
             const float* __restrict__ ref,
             const float* __restrict__ W_off,
             const float* __restrict__ b_off,
             const float* __restrict__ W_attn,
             const float* __restrict__ b_attn,
             const float* __restrict__ W_val,
             const float* __restrict__ b_val,
             const float* __restrict__ W_out,
             const float* __restrict__ b_out,
             const float* __restrict__ W_proj,
             float* __restrict__ out,
             float* __restrict__ out_idx,
             int n_idx,
             float* __restrict__ tailp,
             int tail_n) {
    // Query-PAIR processing: msda kept as raw __half2 (bit-lossless vs fp16
    // accumulators) so two queries fit; all W matrices read ONCE per pair.
    __shared__ __half2 s_msda[2][NL * 64];   // 25.6 KB
    __shared__ float s_q[2][D];
    __shared__ float s_avg[2][D];
    __shared__ float s_off[2][64];
    __shared__ float s_aw[2][32];
    __shared__ float s_wp[D];
    __shared__ float s_wts[2][64];
    __shared__ float s_refy[2][NL];
    __shared__ float s_refx[2];
    __shared__ float s_part[2][D];
    __shared__ float s_wx[2][64];
    __shared__ int   s_cx[2][64];
    __shared__ float s_lg[2][NL];
    __shared__ float s_val[2 * D];

    const __half* __restrict__ proj = g_projh;
    int tid = threadIdx.x;

    // ===================== wp = W_out @ W_proj (needed in phase 0) ==========
    {
        if (tid < D) s_avg[0][tid] = W_proj[tid];
        __syncthreads();
        int warp = tid >> 5, lane = tid & 31;
        for (int r = warp; r < D; r += 8) {
            float a = 0.f;
#pragma unroll
            for (int kk = 0; kk < 4; kk++) {
                int k = lane + kk * 32;
                a = fmaf(W_out[r * D + k], s_avg[0][k], a);
            }
#pragma unroll
            for (int o = 16; o; o >>= 1)
                a += __shfl_down_sync(0xffffffffu, a, o);
            if (lane == 0) s_wp[r] = a;
        }
        __syncthreads();
    }

    // ===================== phase 0: value projection (fp32->fp16 + G) =======
    {
        int ch = tid & 127;
        int half_ = tid >> 7;
        float wpc = s_wp[ch];
        for (int s0 = blockIdx.x * 2; s0 < HW; s0 += GRID * 2) {
            int s = s0 + half_;
            bool ok = s < HW;
            __syncthreads();
            if (ok) s_val[half_ * D + ch] = value[s * D + ch];
            __syncthreads();
            float acc = 0.f;
            if (ok) {
                acc = b_val[ch];
                const float* vr = &s_val[half_ * D];
#pragma unroll 8
                for (int k = 0; k < D; k++)
                    acc = fmaf(vr[k], W_val[k * D + ch], acc);
                g_projh[(ch >> 4) * (HW * HD) + s * HD + (ch & 15)] =
                    __float2half(acc);
            }
            float gterm = acc * wpc;
#pragma unroll
            for (int o = 1; o < 16; o <<= 1)
                gterm += __shfl_xor_sync(0xffffffffu, gterm, o);
            if (ok && (tid & 15) == 0)
                g_G[(ch >> 4) * HW + s] = gterm;
        }
        for (int i = blockIdx.x * TPB + tid; i < tail_n; i += GRID * TPB)
            tailp[i] = 0.f;
    }

    // ===================== device-wide barrier ==============================
    __syncthreads();
    if (tid == 0) {
        __threadfence();
        atomicAdd(&g_arrive, 1u);
        while (*(volatile unsigned*)&g_arrive < GRID) { }
        __threadfence();
        unsigned old = atomicAdd(&g_depart, 1u);
        if (old == GRID - 1) {
            *(volatile unsigned*)&g_arrive = 0u;
            __threadfence();
            *(volatile unsigned*)&g_depart = 0u;
        }
    }
    __syncthreads();

    // ===================== phase 1: per-PAIR attention ======================
    for (int q0 = blockIdx.x * 2; q0 < NQ; q0 += GRID * 2) {
        __syncthreads();
        {
            int qi = tid >> 7, ch = tid & 127;
            s_q[qi][ch] = query[(q0 + qi) * D + ch];
        }
        __syncthreads();

        // ---- offsets (64) + attn logits (32) for BOTH queries, one W read;
        //      warps 6-7 load ref y/x for both queries.
        if (tid < 192) {
            int col = tid >> 1;
            int half_ = tid & 1;
            bool is_off = col < 64;
            const float* W = is_off ? (W_off + col) : (W_attn + (col - 64));
            int stride = is_off ? 64 : 32;
            float a0 = 0.f;
            if (half_ == 0)
                a0 = is_off ? b_off[col] : b_attn[col - 64];
            float a1 = a0;
            int k0 = half_ * 64;
#pragma unroll 8
            for (int k = 0; k < 64; k++) {
                float w = W[(k0 + k) * stride];
                a0 = fmaf(s_q[0][k0 + k], w, a0);
                a1 = fmaf(s_q[1][k0 + k], w, a1);
            }
            a0 += __shfl_xor_sync(0xffffffffu, a0, 1);
            a1 += __shfl_xor_sync(0xffffffffu, a1, 1);
            if (half_ == 0) {
                if (is_off) {
                    float nrm = (col & 1) ? (float)HSP : (float)WSP;
                    s_off[0][col] = a0 / nrm;
                    s_off[1][col] = a1 / nrm;
                } else {
                    s_aw[0][col - 64] = a0;
                    s_aw[1][col - 64] = a1;
                }
            }
        } else {
            for (int i = tid - 192; i < 2 * NL + 2; i += 64) {
                if (i < 2 * NL) {
                    int qi = i >= NL;
                    int l = i - qi * NL;
                    s_refy[qi][l] = ref[l * (NQ * 2) + (q0 + qi) * 2 + 1];
                } else {
                    s_refx[i - 2 * NL] = ref[(q0 + (i - 2 * NL)) * 2];
                }
            }
        }
        __syncthreads();

        // ---- point softmax (tid<16: qi,h) + x precompute (tid 32..95: qi,up)
        if (tid < 16) {
            int qi = tid >> 3, h = tid & 7;
            float m = s_aw[qi][h * 4];
#pragma unroll
            for (int p = 1; p < 4; p++) m = fmaxf(m, s_aw[qi][h * 4 + p]);
            float e[4]; float ssum = 0.f;
#pragma unroll
            for (int p = 0; p < 4; p++) {
                e[p] = expf(s_aw[qi][h * 4 + p] - m);
                ssum += e[p];
            }
            float inv = 1.f / ssum;
#pragma unroll
            for (int p = 0; p < 4; p++) s_aw[qi][h * 4 + p] = e[p] * inv;
        } else if (tid >= 32 && tid < 96) {
            int qi = (tid - 32) >> 5, up = (tid - 32) & 31;
            float px = (s_refx[qi] + s_off[qi][up * 2]) * (float)WSP - 0.5f;
            float x0f = floorf(px);
            float dx = px - x0f;
            int x0 = (int)x0f;
            s_wx[qi][up * 2 + 0] = ((unsigned)x0 < WSP) ? (1.f - dx) : 0.f;
            s_wx[qi][up * 2 + 1] = ((unsigned)(x0 + 1) < WSP) ? dx : 0.f;
            s_cx[qi][up * 2 + 0] = min(max(x0, 0), WSP - 1);
            s_cx[qi][up * 2 + 1] = min(max(x0 + 1, 0), WSP - 1);
        }
        __syncthreads();

        // ---- MSDA channel sampling (fp16, R9 shape) with per-head constants
        //      HOISTED to registers (removes ~16 LDS per unit-iteration).
        {
            int j = tid & 3;
            int slot = tid >> 2;             // 0..63
            int xc = j >> 1;
            int co = (j & 1) * 8;
            int h = slot & 7;                // loop-invariant head
            const __half* basep = proj + h * (HW * HD) + co;

#pragma unroll 1
            for (int qi = 0; qi < 2; qi++) {
                float wxaw[4], offy[4];
                int cxl[4];
#pragma unroll
                for (int p = 0; p < 4; p++) {
                    int up = h * 4 + p;
                    wxaw[p] = s_wx[qi][up * 2 + xc] * s_aw[qi][up];
                    offy[p] = s_off[qi][up * 2 + 1];
                    cxl[p]  = s_cx[qi][up * 2 + xc];
                }
                for (int u = slot; u < NL * NHEADS; u += 64) {
                    int l = u >> 3;
                    float ry = s_refy[qi][l];
                    __half2 ac0 = __float2half2_rn(0.f);
                    __half2 ac1 = ac0, ac2 = ac0, ac3 = ac0;
#pragma unroll
                    for (int p = 0; p < NPOINTS; p++) {
                        float py = (ry + offy[p]) * (float)HSP - 0.5f;
                        float y0f = floorf(py);
                        float dy = py - y0f;
                        int y0 = (int)y0f;
                        float wy0 = ((unsigned)y0 < HSP) ? (1.f - dy) : 0.f;
                        float wy1 = ((unsigned)(y0 + 1) < HSP) ? dy : 0.f;
                        int cy0 = min(max(y0, 0), HSP - 1);
                        int cy1 = min(max(y0 + 1, 0), HSP - 1);
                        uint4 v0 = *(const uint4*)(basep + (cy0 * WSP + cxl[p]) * HD);
                        uint4 v1 = *(const uint4*)(basep + (cy1 * WSP + cxl[p]) * HD);
                        __half2 w0 = __float2half2_rn(wxaw[p] * wy0);
                        __half2 w1 = __float2half2_rn(wxaw[p] * wy1);
                        ac0 = __hfma2(*(__half2*)&v0.x, w0, ac0);
                        ac1 = __hfma2(*(__half2*)&v0.y, w0, ac1);
                        ac2 = __hfma2(*(__half2*)&v0.z, w0, ac2);
                        ac3 = __hfma2(*(__half2*)&v0.w, w0, ac3);
                        ac0 = __hfma2(*(__half2*)&v1.x, w1, ac0);
                        ac1 = __hfma2(*(__half2*)&v1.y, w1, ac1);
                        ac2 = __hfma2(*(__half2*)&v1.z, w1, ac2);
                        ac3 = __hfma2(*(__half2*)&v1.w, w1, ac3);
                    }
                    unsigned t;
                    t = __shfl_xor_sync(0xffffffffu, *(unsigned*)&ac0, 2);
                    ac0 = __hadd2(ac0, *(__half2*)&t);
                    t = __shfl_xor_sync(0xffffffffu, *(unsigned*)&ac1, 2);
                    ac1 = __hadd2(ac1, *(__half2*)&t);
                    t = __shfl_xor_sync(0xffffffffu, *(unsigned*)&ac2, 2);
                    ac2 = __hadd2(ac2, *(__half2*)&t);
                    t = __shfl_xor_sync(0xffffffffu, *(unsigned*)&ac3, 2);
                    ac3 = __hadd2(ac3, *(__half2*)&t);
                    if (j < 2) {
                        uint4 pk;
                        pk.x = *(unsigned*)&ac0;
                        pk.y = *(unsigned*)&ac1;
                        pk.z = *(unsigned*)&ac2;
                        pk.w = *(unsigned*)&ac3;
                        *(uint4*)&s_msda[qi][l * 64 + h * 8 + (j & 1) * 4] = pk;
                    }
                }
            }

            // ---- exact fp32 level logits: warp = level, lane = (h,p)
            int warp = tid >> 5;
            int lane = tid & 31;
            int hh = lane >> 2;
            const float* Gh = g_G + hh * HW;
#pragma unroll 1
            for (int qi = 0; qi < 2; qi++) {
                float wx0 = s_wx[qi][lane * 2 + 0];
                float wx1 = s_wx[qi][lane * 2 + 1];
                int cx0 = s_cx[qi][lane * 2 + 0];
                int cx1 = s_cx[qi][lane * 2 + 1];
                float goffy = s_off[qi][lane * 2 + 1];
                float awl = s_aw[qi][lane];
                for (int l = warp; l < NL; l += 8) {
                    float py = (s_refy[qi][l] + goffy) * (float)HSP - 0.5f;
                    float y0f = floorf(py);
                    float dy = py - y0f;
                    int y0 = (int)y0f;
                    float wy0 = ((unsigned)y0 < HSP) ? (1.f - dy) : 0.f;
                    float wy1 = ((unsigned)(y0 + 1) < HSP) ? dy : 0.f;
                    int cy0 = min(max(y0, 0), HSP - 1);
                    int cy1 = min(max(y0 + 1, 0), HSP - 1);
                    const float* r0 = Gh + cy0 * WSP;
                    const float* r1 = Gh + cy1 * WSP;
                    float g00 = r0[cx0], g01 = r0[cx1];
                    float g10 = r1[cx0], g11 = r1[cx1];
                    float t = awl * (wy0 * fmaf(wx0, g00, wx1 * g01)
                                   + wy1 * fmaf(wx0, g10, wx1 * g11));
#pragma unroll
                    for (int o = 16; o; o >>= 1)
                        t += __shfl_xor_sync(0xffffffffu, t, o);
                    if (lane == 0) s_lg[qi][l] = t;
                }
            }
        }
        __syncthreads();

        // ---- level softmax + argmax: warps 0-1 (one per query), parallel
        if (tid < 64) {
            int qi = tid >> 5, lane = tid & 31;
            float v0 = (lane < NL) ? s_lg[qi][lane] : -3.4e38f;
            float v1 = (lane + 32 < NL) ? s_lg[qi][lane + 32] : -3.4e38f;
            float bv; int bi;
            if (v1 > v0) { bv = v1; bi = lane + 32; }
            else         { bv = v0; bi = lane; }
#pragma unroll
            for (int o = 16; o; o >>= 1) {
                float ov = __shfl_down_sync(0xffffffffu, bv, o);
                int   oi = __shfl_down_sync(0xffffffffu, bi, o);
                if (ov > bv || (ov == bv && oi < bi)) { bv = ov; bi = oi; }
            }
            bv = __shfl_sync(0xffffffffu, bv, 0);
            float e0 = (lane < NL) ? expf(v0 - bv) : 0.f;
            float e1 = (lane + 32 < NL) ? expf(v1 - bv) : 0.f;
            float ssum = e0 + e1;
#pragma unroll
            for (int o = 16; o; o >>= 1)
                ssum += __shfl_xor_sync(0xffffffffu, ssum, o);
            float inv = 1.f / ssum;
            if (lane < NL) s_wts[qi][lane] = e0 * inv;
            if (lane + 32 < NL) s_wts[qi][lane + 32] = e1 * inv;
            if (lane == 0 && (q0 + qi) < n_idx) out_idx[q0 + qi] = (float)bi;
        }
        __syncthreads();

        // ---- weighted average over levels (256 threads: qi x 128 ch)
        {
            int qi = tid >> 7, ch = tid & 127;
            float acc = 0.f;
#pragma unroll 5
            for (int l = 0; l < NL; l++) {
                __half2 hv = s_msda[qi][l * 64 + (ch >> 1)];
                float v = (ch & 1) ? __high2float(hv) : __low2float(hv);
                acc = fmaf(s_wts[qi][l], v, acc);
            }
            s_avg[qi][ch] = acc;
        }
        __syncthreads();

        // ---- final GEMV for BOTH queries, one W_out read (k-split)
        {
            int ch = tid & 127, half_ = tid >> 7;
            int k0 = half_ * 64;
            float a0 = 0.f, a1 = 0.f;
#pragma unroll 8
            for (int k = 0; k < 64; k++) {
                float w = W_out[(k0 + k) * D + ch];
                a0 = fmaf(s_avg[0][k0 + k], w, a0);
                a1 = fmaf(s_avg[1][k0 + k], w, a1);
            }
            if (half_) { s_part[0][ch] = a0; s_part[1][ch] = a1; }
            __syncthreads();
            if (!half_) {
                float b = b_out[ch];
                out[q0 * D + ch] =
                    a0 + s_part[0][ch] + b + 2.0f * s_q[0][ch];
                out[(q0 + 1) * D + ch] =
                    a1 + s_part[1][ch] + b + 2.0f * s_q[1][ch];
            }
        }
    }
}

// ---------------------------------------------------------------------------
extern "C" void kernel_launch(void* const* d_in, const int* in_sizes, int n_in,
                              void* d_out, int out_size) {
    const float* query  = (const float*)d_in[0];
    const float* value  = (const float*)d_in[1];
    const float* refp   = (const float*)d_in[2];
    const float* W_off  = (const float*)d_in[3];
    const float* b_off  = (const float*)d_in[4];
    const float* W_attn = (const float*)d_in[5];
    const float* b_attn = (const float*)d_in[6];
    const float* W_val  = (const float*)d_in[7];
    const float* b_val  = (const float*)d_in[8];
    const float* W_out  = (const float*)d_in[9];
    const float* b_out  = (const float*)d_in[10];
    const float* W_proj = (const float*)d_in[11];
    // b_proj (d_in[12]) unused: constant shift is softmax/argmax-invariant.

    float* out = (float*)d_out;

    int n_idx = out_size - NQ * D;
    if (n_idx < 0) n_idx = 0;
    if (n_idx > NQ) n_idx = NQ;

    int tail_n = out_size - (NQ * D + NQ);
    float* tailp = out + NQ * D + NQ;
    if (tail_n < 0) { tail_n = 0; tailp = out; }

    fused_kernel<<<GRID, TPB>>>(query, value, refp, W_off, b_off,
                                W_attn, b_attn, W_val, b_val,
                                W_out, b_out, W_proj,
                                out, out + NQ * D, n_idx, tailp, tail_n);
}

// round 13
// speedup vs baseline: 1.4352x; 1.1888x over previous
#include <cuda_runtime.h>
#include <cuda_fp16.h>

#define NQ      10000
#define D       128
#define NHEADS  8
#define NPOINTS 4
#define HSP     51
#define WSP     102
#define HW      (HSP * WSP)
#define NL      50
#define HD      16
#define TPB     256
#define GRID    592
#define QB      4

// Scratch (device globals; no allocation allowed). Head-major (best measured).
__device__ __align__(128) __half g_projh[NHEADS * HW * HD];  // fp16 1.33MB
__device__ float g_G[NHEADS * HW];    // fp32 scalar field [h][y*W+x]
__device__ unsigned g_arrive = 0;
__device__ unsigned g_depart = 0;

// ---------------------------------------------------------------------------
__global__ void __launch_bounds__(TPB, 4)
fused_kernel(const float* __restrict__ query,
             const float* __restrict__ value,
             const float* __restrict__ ref,
             const float* __restrict__ W_off,
             const float* __restrict__ b_off,
             const float* __restrict__ W_attn,
             const float* __restrict__ b_attn,
             const float* __restrict__ W_val,
             const float* __restrict__ b_val,
             const float* __restrict__ W_out,
             const float* __restrict__ b_out,
             const float* __restrict__ W_proj,
             float* __restrict__ out,
             float* __restrict__ out_idx,
             int n_idx,
             float* __restrict__ tailp,
             int tail_n) {
    // 4-query batches; level weights computed BEFORE sampling so the gather
    // accumulates w_l * sample directly (no msda buffer, no 50-LDS avg pass).
    __shared__ float s_pavg[QB][8][D];    // 16 KB per-warp partial averages
    __shared__ float s_q[QB][D];
    __shared__ float s_avg[QB][D];
    __shared__ float s_off[QB][64];
    __shared__ float s_aw[QB][32];
    __shared__ float s_wp[D];
    __shared__ float s_wts[QB][64];
    __shared__ float s_refy[QB][NL];
    __shared__ float s_refx[QB];
    __shared__ float s_part[QB][D];
    __shared__ float s_wx[QB][64];
    __shared__ int   s_cx[QB][64];
    __shared__ float s_lg[QB][NL];
    __shared__ float s_val[2 * D];

    const __half* __restrict__ proj = g_projh;
    int tid = threadIdx.x;

    // ===================== wp = W_out @ W_proj (needed in phase 0) ==========
    {
        if (tid < D) s_avg[0][tid] = W_proj[tid];
        __syncthreads();
        int warp = tid >> 5, lane = tid & 31;
        for (int r = warp; r < D; r += 8) {
            float a = 0.f;
#pragma unroll
            for (int kk = 0; kk < 4; kk++) {
                int k = lane + kk * 32;
                a = fmaf(W_out[r * D + k], s_avg[0][k], a);
            }
#pragma unroll
            for (int o = 16; o; o >>= 1)
                a += __shfl_down_sync(0xffffffffu, a, o);
            if (lane == 0) s_wp[r] = a;
        }
        __syncthreads();
    }

    // ===================== phase 0: value projection (fp32->fp16 + G) =======
    {
        int ch = tid & 127;
        int half_ = tid >> 7;
        float wpc = s_wp[ch];
        for (int s0 = blockIdx.x * 2; s0 < HW; s0 += GRID * 2) {
            int s = s0 + half_;
            bool ok = s < HW;
            __syncthreads();
            if (ok) s_val[half_ * D + ch] = value[s * D + ch];
            __syncthreads();
            float acc = 0.f;
            if (ok) {
                acc = b_val[ch];
                const float* vr = &s_val[half_ * D];
#pragma unroll 8
                for (int k = 0; k < D; k++)
                    acc = fmaf(vr[k], W_val[k * D + ch], acc);
                g_projh[(ch >> 4) * (HW * HD) + s * HD + (ch & 15)] =
                    __float2half(acc);
            }
            float gterm = acc * wpc;
#pragma unroll
            for (int o = 1; o < 16; o <<= 1)
                gterm += __shfl_xor_sync(0xffffffffu, gterm, o);
            if (ok && (tid & 15) == 0)
                g_G[(ch >> 4) * HW + s] = gterm;
        }
        for (int i = blockIdx.x * TPB + tid; i < tail_n; i += GRID * TPB)
            tailp[i] = 0.f;
    }

    // ===================== device-wide barrier ==============================
    __syncthreads();
    if (tid == 0) {
        __threadfence();
        atomicAdd(&g_arrive, 1u);
        while (*(volatile unsigned*)&g_arrive < GRID) { }
        __threadfence();
        unsigned old = atomicAdd(&g_depart, 1u);
        if (old == GRID - 1) {
            *(volatile unsigned*)&g_arrive = 0u;
            __threadfence();
            *(volatile unsigned*)&g_depart = 0u;
        }
    }
    __syncthreads();

    // ===================== phase 1: 4-query batches =========================
    for (int q0 = blockIdx.x * QB; q0 < NQ; q0 += GRID * QB) {
        __syncthreads();
        for (int i = tid; i < QB * D; i += TPB)
            s_q[i >> 7][i & 127] = query[q0 * D + i];
        __syncthreads();

        // ---- offsets (64) + attn logits (32) for ALL 4 queries, one W read
        if (tid < 192) {
            int col = tid >> 1;
            int half_ = tid & 1;
            bool is_off = col < 64;
            const float* W = is_off ? (W_off + col) : (W_attn + (col - 64));
            int stride = is_off ? 64 : 32;
            float b = 0.f;
            if (half_ == 0)
                b = is_off ? b_off[col] : b_attn[col - 64];
            float a0 = b, a1 = b, a2 = b, a3 = b;
            int k0 = half_ * 64;
#pragma unroll 8
            for (int k = 0; k < 64; k++) {
                float w = W[(k0 + k) * stride];
                a0 = fmaf(s_q[0][k0 + k], w, a0);
                a1 = fmaf(s_q[1][k0 + k], w, a1);
                a2 = fmaf(s_q[2][k0 + k], w, a2);
                a3 = fmaf(s_q[3][k0 + k], w, a3);
            }
            a0 += __shfl_xor_sync(0xffffffffu, a0, 1);
            a1 += __shfl_xor_sync(0xffffffffu, a1, 1);
            a2 += __shfl_xor_sync(0xffffffffu, a2, 1);
            a3 += __shfl_xor_sync(0xffffffffu, a3, 1);
            if (half_ == 0) {
                if (is_off) {
                    float nrm = (col & 1) ? (float)HSP : (float)WSP;
                    s_off[0][col] = a0 / nrm;
                    s_off[1][col] = a1 / nrm;
                    s_off[2][col] = a2 / nrm;
                    s_off[3][col] = a3 / nrm;
                } else {
                    s_aw[0][col - 64] = a0;
                    s_aw[1][col - 64] = a1;
                    s_aw[2][col - 64] = a2;
                    s_aw[3][col - 64] = a3;
                }
            }
        } else {
            for (int i = tid - 192; i < QB * NL + QB; i += 64) {
                if (i < QB * NL) {
                    int qi = i / NL;
                    int l = i - qi * NL;
                    s_refy[qi][l] = ref[l * (NQ * 2) + (q0 + qi) * 2 + 1];
                } else {
                    int qi = i - QB * NL;
                    s_refx[qi] = ref[(q0 + qi) * 2];
                }
            }
        }
        __syncthreads();

        // ---- point softmax (tid<32: qi,h) + x precompute (tid 32..159)
        if (tid < 32) {
            int qi = tid >> 3, h = tid & 7;
            float m = s_aw[qi][h * 4];
#pragma unroll
            for (int p = 1; p < 4; p++) m = fmaxf(m, s_aw[qi][h * 4 + p]);
            float e[4]; float ssum = 0.f;
#pragma unroll
            for (int p = 0; p < 4; p++) {
                e[p] = expf(s_aw[qi][h * 4 + p] - m);
                ssum += e[p];
            }
            float inv = 1.f / ssum;
#pragma unroll
            for (int p = 0; p < 4; p++) s_aw[qi][h * 4 + p] = e[p] * inv;
        } else if (tid < 160) {
            int idx = tid - 32;
            int qi = idx >> 5, up = idx & 31;
            float px = (s_refx[qi] + s_off[qi][up * 2]) * (float)WSP - 0.5f;
            float x0f = floorf(px);
            float dx = px - x0f;
            int x0 = (int)x0f;
            s_wx[qi][up * 2 + 0] = ((unsigned)x0 < WSP) ? (1.f - dx) : 0.f;
            s_wx[qi][up * 2 + 1] = ((unsigned)(x0 + 1) < WSP) ? dx : 0.f;
            s_cx[qi][up * 2 + 0] = min(max(x0, 0), WSP - 1);
            s_cx[qi][up * 2 + 1] = min(max(x0 + 1, 0), WSP - 1);
        }
        __syncthreads();

        // ---- exact fp32 level logits FIRST: warp = level, lane = (h,p)
        {
            int warp = tid >> 5, lane = tid & 31;
            int hh = lane >> 2;
            const float* Gh = g_G + hh * HW;
#pragma unroll 1
            for (int qi = 0; qi < QB; qi++) {
                float wx0 = s_wx[qi][lane * 2 + 0];
                float wx1 = s_wx[qi][lane * 2 + 1];
                int cx0 = s_cx[qi][lane * 2 + 0];
                int cx1 = s_cx[qi][lane * 2 + 1];
                float goffy = s_off[qi][lane * 2 + 1];
                float awl = s_aw[qi][lane];
                for (int l = warp; l < NL; l += 8) {
                    float py = (s_refy[qi][l] + goffy) * (float)HSP - 0.5f;
                    float y0f = floorf(py);
                    float dy = py - y0f;
                    int y0 = (int)y0f;
                    float wy0 = ((unsigned)y0 < HSP) ? (1.f - dy) : 0.f;
                    float wy1 = ((unsigned)(y0 + 1) < HSP) ? dy : 0.f;
                    int cy0 = min(max(y0, 0), HSP - 1);
                    int cy1 = min(max(y0 + 1, 0), HSP - 1);
                    const float* r0 = Gh + cy0 * WSP;
                    const float* r1 = Gh + cy1 * WSP;
                    float g00 = r0[cx0], g01 = r0[cx1];
                    float g10 = r1[cx0], g11 = r1[cx1];
                    float t = awl * (wy0 * fmaf(wx0, g00, wx1 * g01)
                                   + wy1 * fmaf(wx0, g10, wx1 * g11));
#pragma unroll
                    for (int o = 16; o; o >>= 1)
                        t += __shfl_xor_sync(0xffffffffu, t, o);
                    if (lane == 0) s_lg[qi][l] = t;
                }
            }
        }
        __syncthreads();

        // ---- level softmax + argmax: warps 0-3 (one per query)
        if (tid < 32 * QB) {
            int qi = tid >> 5, lane = tid & 31;
            float v0 = (lane < NL) ? s_lg[qi][lane] : -3.4e38f;
            float v1 = (lane + 32 < NL) ? s_lg[qi][lane + 32] : -3.4e38f;
            float bv; int bi;
            if (v1 > v0) { bv = v1; bi = lane + 32; }
            else         { bv = v0; bi = lane; }
#pragma unroll
            for (int o = 16; o; o >>= 1) {
                float ov = __shfl_down_sync(0xffffffffu, bv, o);
                int   oi = __shfl_down_sync(0xffffffffu, bi, o);
                if (ov > bv || (ov == bv && oi < bi)) { bv = ov; bi = oi; }
            }
            bv = __shfl_sync(0xffffffffu, bv, 0);
            float e0 = (lane < NL) ? expf(v0 - bv) : 0.f;
            float e1 = (lane + 32 < NL) ? expf(v1 - bv) : 0.f;
            float ssum = e0 + e1;
#pragma unroll
            for (int o = 16; o; o >>= 1)
                ssum += __shfl_xor_sync(0xffffffffu, ssum, o);
            float inv = 1.f / ssum;
            if (lane < NL) s_wts[qi][lane] = e0 * inv;
            if (lane + 32 < NL) s_wts[qi][lane + 32] = e1 * inv;
            if (lane == 0 && (q0 + qi) < n_idx) out_idx[q0 + qi] = (float)bi;
        }
        __syncthreads();

        // ---- sampling with DIRECT weighted accumulation (no msda buffer)
        {
            int j = tid & 3;
            int slot = tid >> 2;             // 0..63
            int xc = j >> 1;
            int co = (j & 1) * 8;
            int h = slot & 7;                // loop-invariant head
            int warp = tid >> 5;
            const __half* basep = proj + h * (HW * HD) + co;

#pragma unroll 1
            for (int qi = 0; qi < QB; qi++) {
                float wxaw[4], offy[4];
                int cxl[4];
#pragma unroll
                for (int p = 0; p < 4; p++) {
                    int up = h * 4 + p;
                    wxaw[p] = s_wx[qi][up * 2 + xc] * s_aw[qi][up];
                    offy[p] = s_off[qi][up * 2 + 1];
                    cxl[p]  = s_cx[qi][up * 2 + xc];
                }
                float f0 = 0.f, f1 = 0.f, f2 = 0.f, f3 = 0.f;
                float f4 = 0.f, f5 = 0.f, f6 = 0.f, f7 = 0.f;
                for (int u = slot; u < NL * NHEADS; u += 64) {
                    int l = u >> 3;
                    float ry = s_refy[qi][l];
                    float wl = s_wts[qi][l];
                    __half2 ac0 = __float2half2_rn(0.f);
                    __half2 ac1 = ac0, ac2 = ac0, ac3 = ac0;
#pragma unroll
                    for (int p = 0; p < NPOINTS; p++) {
                        float py = (ry + offy[p]) * (float)HSP - 0.5f;
                        float y0f = floorf(py);
                        float dy = py - y0f;
                        int y0 = (int)y0f;
                        float wy0 = ((unsigned)y0 < HSP) ? (1.f - dy) : 0.f;
                        float wy1 = ((unsigned)(y0 + 1) < HSP) ? dy : 0.f;
                        int cy0 = min(max(y0, 0), HSP - 1);
                        int cy1 = min(max(y0 + 1, 0), HSP - 1);
                        uint4 v0 = *(const uint4*)(basep + (cy0 * WSP + cxl[p]) * HD);
                        uint4 v1 = *(const uint4*)(basep + (cy1 * WSP + cxl[p]) * HD);
                        __half2 w0 = __float2half2_rn(wxaw[p] * wy0);
                        __half2 w1 = __float2half2_rn(wxaw[p] * wy1);
                        ac0 = __hfma2(*(__half2*)&v0.x, w0, ac0);
                        ac1 = __hfma2(*(__half2*)&v0.y, w0, ac1);
                        ac2 = __hfma2(*(__half2*)&v0.z, w0, ac2);
                        ac3 = __hfma2(*(__half2*)&v0.w, w0, ac3);
                        ac0 = __hfma2(*(__half2*)&v1.x, w1, ac0);
                        ac1 = __hfma2(*(__half2*)&v1.y, w1, ac1);
                        ac2 = __hfma2(*(__half2*)&v1.z, w1, ac2);
                        ac3 = __hfma2(*(__half2*)&v1.w, w1, ac3);
                    }
                    // combine x-corner halves (lanes j and j^2)
                    unsigned t;
                    t = __shfl_xor_sync(0xffffffffu, *(unsigned*)&ac0, 2);
                    ac0 = __hadd2(ac0, *(__half2*)&t);
                    t = __shfl_xor_sync(0xffffffffu, *(unsigned*)&ac1, 2);
                    ac1 = __hadd2(ac1, *(__half2*)&t);
                    t = __shfl_xor_sync(0xffffffffu, *(unsigned*)&ac2, 2);
                    ac2 = __hadd2(ac2, *(__half2*)&t);
                    t = __shfl_xor_sync(0xffffffffu, *(unsigned*)&ac3, 2);
                    ac3 = __hadd2(ac3, *(__half2*)&t);
                    // fp32 weighted accumulation (same values as msda path)
                    float2 c0 = __half22float2(ac0);
                    float2 c1 = __half22float2(ac1);
                    float2 c2 = __half22float2(ac2);
                    float2 c3 = __half22float2(ac3);
                    f0 = fmaf(wl, c0.x, f0); f1 = fmaf(wl, c0.y, f1);
                    f2 = fmaf(wl, c1.x, f2); f3 = fmaf(wl, c1.y, f3);
                    f4 = fmaf(wl, c2.x, f4); f5 = fmaf(wl, c2.y, f5);
                    f6 = fmaf(wl, c3.x, f6); f7 = fmaf(wl, c3.y, f7);
                }
                if (j < 2) {
                    float4 w_;
                    w_.x = f0; w_.y = f1; w_.z = f2; w_.w = f3;
                    *(float4*)&s_pavg[qi][warp][h * HD + co] = w_;
                    float4 w2_;
                    w2_.x = f4; w2_.y = f5; w2_.z = f6; w2_.w = f7;
                    *(float4*)&s_pavg[qi][warp][h * HD + co + 4] = w2_;
                }
            }
        }
        __syncthreads();

        // ---- reduce 8 warp-partials -> s_avg (8 LDS per channel, not 50)
        for (int i = tid; i < QB * D; i += TPB) {
            int qi = i >> 7, ch = i & 127;
            float acc = 0.f;
#pragma unroll
            for (int w = 0; w < 8; w++)
                acc += s_pavg[qi][w][ch];
            s_avg[qi][ch] = acc;
        }
        __syncthreads();

        // ---- final GEMV for ALL 4 queries, one W_out read (k-split)
        {
            int ch = tid & 127, half_ = tid >> 7;
            int k0 = half_ * 64;
            float a0 = 0.f, a1 = 0.f, a2 = 0.f, a3 = 0.f;
#pragma unroll 8
            for (int k = 0; k < 64; k++) {
                float w = W_out[(k0 + k) * D + ch];
                a0 = fmaf(s_avg[0][k0 + k], w, a0);
                a1 = fmaf(s_avg[1][k0 + k], w, a1);
                a2 = fmaf(s_avg[2][k0 + k], w, a2);
                a3 = fmaf(s_avg[3][k0 + k], w, a3);
            }
            if (half_) {
                s_part[0][ch] = a0; s_part[1][ch] = a1;
                s_part[2][ch] = a2; s_part[3][ch] = a3;
            }
            __syncthreads();
            if (!half_) {
                float b = b_out[ch];
                out[(q0 + 0) * D + ch] = a0 + s_part[0][ch] + b + 2.0f * s_q[0][ch];
                out[(q0 + 1) * D + ch] = a1 + s_part[1][ch] + b + 2.0f * s_q[1][ch];
                out[(q0 + 2) * D + ch] = a2 + s_part[2][ch] + b + 2.0f * s_q[2][ch];
                out[(q0 + 3) * D + ch] = a3 + s_part[3][ch] + b + 2.0f * s_q[3][ch];
            }
        }
    }
}

// ---------------------------------------------------------------------------
extern "C" void kernel_launch(void* const* d_in, const int* in_sizes, int n_in,
                              void* d_out, int out_size) {
    const float* query  = (const float*)d_in[0];
    const float* value  = (const float*)d_in[1];
    const float* refp   = (const float*)d_in[2];
    const float* W_off  = (const float*)d_in[3];
    const float* b_off  = (const float*)d_in[4];
    const float* W_attn = (const float*)d_in[5];
    const float* b_attn = (const float*)d_in[6];
    const float* W_val  = (const float*)d_in[7];
    const float* b_val  = (const float*)d_in[8];
    const float* W_out  = (const float*)d_in[9];
    const float* b_out  = (const float*)d_in[10];
    const float* W_proj = (const float*)d_in[11];
    // b_proj (d_in[12]) unused: constant shift is softmax/argmax-invariant.

    float* out = (float*)d_out;

    int n_idx = out_size - NQ * D;
    if (n_idx < 0) n_idx = 0;
    if (n_idx > NQ) n_idx = NQ;

    int tail_n = out_size - (NQ * D + NQ);
    float* tailp = out + NQ * D + NQ;
    if (tail_n < 0) { tail_n = 0; tailp = out; }

    fused_kernel<<<GRID, TPB>>>(query, value, refp, W_off, b_off,
                                W_attn, b_attn, W_val, b_val,
                                W_out, b_out, W_proj,
                                out, out + NQ * D, n_idx, tailp, tail_n);
}

// round 14
// speedup vs baseline: 1.4478x; 1.0088x over previous
#include <cuda_runtime.h>
#include <cuda_fp16.h>

#define NQ      10000
#define D       128
#define NHEADS  8
#define NPOINTS 4
#define HSP     51
#define WSP     102
#define HW      (HSP * WSP)
#define NL      50
#define HD      16
#define TPB     256
#define GRID    592
#define QB      8

// Scratch (device globals; no allocation allowed). Head-major (best measured).
__device__ __align__(128) __half g_projh[NHEADS * HW * HD];  // fp16 1.33MB
__device__ float g_G[NHEADS * HW];    // fp32 scalar field [h][y*W+x]
__device__ unsigned g_arrive = 0;
__device__ unsigned g_depart = 0;
__device__ unsigned g_qctr = 0;       // work-stealing batch counter

// ---------------------------------------------------------------------------
__global__ void __launch_bounds__(TPB, 4)
fused_kernel(const float* __restrict__ query,
             const float* __restrict__ value,
             const float* __restrict__ ref,
             const float* __restrict__ W_off,
             const float* __restrict__ b_off,
             const float* __restrict__ W_attn,
             const float* __restrict__ b_attn,
             const float* __restrict__ W_val,
             const float* __restrict__ b_val,
             const float* __restrict__ W_out,
             const float* __restrict__ b_out,
             const float* __restrict__ W_proj,
             float* __restrict__ out,
             float* __restrict__ out_idx,
             int n_idx,
             float* __restrict__ tailp,
             int tail_n) {
    __shared__ float s_pavg[8][D];        // 4 KB, per-warp partials (one qi)
    __shared__ float s_q[QB][D];
    __shared__ float s_avg[QB][D];
    __shared__ float s_off[QB][64];
    __shared__ float s_aw[QB][32];
    __shared__ float s_wp[D];
    __shared__ float s_wts[QB][64];
    __shared__ float s_refy[QB][NL];
    __shared__ float s_refx[QB];
    __shared__ float s_part[QB][D];
    __shared__ float s_wx[QB][64];
    __shared__ int   s_cx[QB][64];
    __shared__ float s_lg[QB][NL];
    __shared__ float s_val[2 * D];
    __shared__ int   s_qbase;

    const __half* __restrict__ proj = g_projh;
    int tid = threadIdx.x;

    // ===================== wp = W_out @ W_proj (needed in phase 0) ==========
    {
        if (tid < D) s_avg[0][tid] = W_proj[tid];
        __syncthreads();
        int warp = tid >> 5, lane = tid & 31;
        for (int r = warp; r < D; r += 8) {
            float a = 0.f;
#pragma unroll
            for (int kk = 0; kk < 4; kk++) {
                int k = lane + kk * 32;
                a = fmaf(W_out[r * D + k], s_avg[0][k], a);
            }
#pragma unroll
            for (int o = 16; o; o >>= 1)
                a += __shfl_down_sync(0xffffffffu, a, o);
            if (lane == 0) s_wp[r] = a;
        }
        __syncthreads();
    }

    // ===================== phase 0: value projection (fp32->fp16 + G) =======
    {
        if (blockIdx.x == 0 && tid == 0) g_qctr = 0;   // reset per launch
        int ch = tid & 127;
        int half_ = tid >> 7;
        float wpc = s_wp[ch];
        for (int s0 = blockIdx.x * 2; s0 < HW; s0 += GRID * 2) {
            int s = s0 + half_;
            bool ok = s < HW;
            __syncthreads();
            if (ok) s_val[half_ * D + ch] = value[s * D + ch];
            __syncthreads();
            float acc = 0.f;
            if (ok) {
                acc = b_val[ch];
                const float* vr = &s_val[half_ * D];
#pragma unroll 8
                for (int k = 0; k < D; k++)
                    acc = fmaf(vr[k], W_val[k * D + ch], acc);
                g_projh[(ch >> 4) * (HW * HD) + s * HD + (ch & 15)] =
                    __float2half(acc);
            }
            float gterm = acc * wpc;
#pragma unroll
            for (int o = 1; o < 16; o <<= 1)
                gterm += __shfl_xor_sync(0xffffffffu, gterm, o);
            if (ok && (tid & 15) == 0)
                g_G[(ch >> 4) * HW + s] = gterm;
        }
        for (int i = blockIdx.x * TPB + tid; i < tail_n; i += GRID * TPB)
            tailp[i] = 0.f;
    }

    // ===================== device-wide barrier ==============================
    __syncthreads();
    if (tid == 0) {
        __threadfence();
        atomicAdd(&g_arrive, 1u);
        while (*(volatile unsigned*)&g_arrive < GRID) { }
        __threadfence();
        unsigned old = atomicAdd(&g_depart, 1u);
        if (old == GRID - 1) {
            *(volatile unsigned*)&g_arrive = 0u;
            __threadfence();
            *(volatile unsigned*)&g_depart = 0u;
        }
    }
    __syncthreads();

    // ===================== phase 1: work-stolen 8-query batches =============
    for (;;) {
        __syncthreads();
        if (tid == 0) s_qbase = (int)atomicAdd(&g_qctr, (unsigned)QB);
        __syncthreads();
        int q0 = s_qbase;
        if (q0 >= NQ) break;

        for (int i = tid; i < QB * D; i += TPB)
            s_q[i >> 7][i & 127] = query[q0 * D + i];
        __syncthreads();

        // ---- offsets (64) + attn logits (32) for ALL 8 queries, one W read
        if (tid < 192) {
            int col = tid >> 1;
            int half_ = tid & 1;
            bool is_off = col < 64;
            const float* W = is_off ? (W_off + col) : (W_attn + (col - 64));
            int stride = is_off ? 64 : 32;
            float b = 0.f;
            if (half_ == 0)
                b = is_off ? b_off[col] : b_attn[col - 64];
            float a[QB];
#pragma unroll
            for (int qi = 0; qi < QB; qi++) a[qi] = b;
            int k0 = half_ * 64;
#pragma unroll 4
            for (int k = 0; k < 64; k++) {
                float w = W[(k0 + k) * stride];
#pragma unroll
                for (int qi = 0; qi < QB; qi++)
                    a[qi] = fmaf(s_q[qi][k0 + k], w, a[qi]);
            }
#pragma unroll
            for (int qi = 0; qi < QB; qi++)
                a[qi] += __shfl_xor_sync(0xffffffffu, a[qi], 1);
            if (half_ == 0) {
                if (is_off) {
                    float nrm = (col & 1) ? (float)HSP : (float)WSP;
#pragma unroll
                    for (int qi = 0; qi < QB; qi++)
                        s_off[qi][col] = a[qi] / nrm;
                } else {
#pragma unroll
                    for (int qi = 0; qi < QB; qi++)
                        s_aw[qi][col - 64] = a[qi];
                }
            }
        } else {
            for (int i = tid - 192; i < QB * NL + QB; i += 64) {
                if (i < QB * NL) {
                    int qi = i / NL;
                    int l = i - qi * NL;
                    s_refy[qi][l] = ref[l * (NQ * 2) + (q0 + qi) * 2 + 1];
                } else {
                    int qi = i - QB * NL;
                    s_refx[qi] = ref[(q0 + qi) * 2];
                }
            }
        }
        __syncthreads();

        // ---- x precompute (all 256: qi x up) then point softmax (tid<64)
        {
            int qi = tid >> 5, up = tid & 31;
            float px = (s_refx[qi] + s_off[qi][up * 2]) * (float)WSP - 0.5f;
            float x0f = floorf(px);
            float dx = px - x0f;
            int x0 = (int)x0f;
            s_wx[qi][up * 2 + 0] = ((unsigned)x0 < WSP) ? (1.f - dx) : 0.f;
            s_wx[qi][up * 2 + 1] = ((unsigned)(x0 + 1) < WSP) ? dx : 0.f;
            s_cx[qi][up * 2 + 0] = min(max(x0, 0), WSP - 1);
            s_cx[qi][up * 2 + 1] = min(max(x0 + 1, 0), WSP - 1);
        }
        if (tid < 64) {
            int qi = tid >> 3, h = tid & 7;
            float m = s_aw[qi][h * 4];
#pragma unroll
            for (int p = 1; p < 4; p++) m = fmaxf(m, s_aw[qi][h * 4 + p]);
            float e[4]; float ssum = 0.f;
#pragma unroll
            for (int p = 0; p < 4; p++) {
                e[p] = expf(s_aw[qi][h * 4 + p] - m);
                ssum += e[p];
            }
            float inv = 1.f / ssum;
#pragma unroll
            for (int p = 0; p < 4; p++) s_aw[qi][h * 4 + p] = e[p] * inv;
        }
        __syncthreads();

        // ---- exact fp32 level logits: warp = level, lane = (h,p)
        {
            int warp = tid >> 5, lane = tid & 31;
            int hh = lane >> 2;
            const float* Gh = g_G + hh * HW;
#pragma unroll 1
            for (int qi = 0; qi < QB; qi++) {
                float wx0 = s_wx[qi][lane * 2 + 0];
                float wx1 = s_wx[qi][lane * 2 + 1];
                int cx0 = s_cx[qi][lane * 2 + 0];
                int cx1 = s_cx[qi][lane * 2 + 1];
                float goffy = s_off[qi][lane * 2 + 1];
                float awl = s_aw[qi][lane];
                for (int l = warp; l < NL; l += 8) {
                    float py = (s_refy[qi][l] + goffy) * (float)HSP - 0.5f;
                    float y0f = floorf(py);
                    float dy = py - y0f;
                    int y0 = (int)y0f;
                    float wy0 = ((unsigned)y0 < HSP) ? (1.f - dy) : 0.f;
                    float wy1 = ((unsigned)(y0 + 1) < HSP) ? dy : 0.f;
                    int cy0 = min(max(y0, 0), HSP - 1);
                    int cy1 = min(max(y0 + 1, 0), HSP - 1);
                    const float* r0 = Gh + cy0 * WSP;
                    const float* r1 = Gh + cy1 * WSP;
                    float g00 = r0[cx0], g01 = r0[cx1];
                    float g10 = r1[cx0], g11 = r1[cx1];
                    float t = awl * (wy0 * fmaf(wx0, g00, wx1 * g01)
                                   + wy1 * fmaf(wx0, g10, wx1 * g11));
#pragma unroll
                    for (int o = 16; o; o >>= 1)
                        t += __shfl_xor_sync(0xffffffffu, t, o);
                    if (lane == 0) s_lg[qi][l] = t;
                }
            }
        }
        __syncthreads();

        // ---- level softmax + argmax: warps 0-7 (one per query)
        {
            int qi = tid >> 5, lane = tid & 31;
            float v0 = (lane < NL) ? s_lg[qi][lane] : -3.4e38f;
            float v1 = (lane + 32 < NL) ? s_lg[qi][lane + 32] : -3.4e38f;
            float bv; int bi;
            if (v1 > v0) { bv = v1; bi = lane + 32; }
            else         { bv = v0; bi = lane; }
#pragma unroll
            for (int o = 16; o; o >>= 1) {
                float ov = __shfl_down_sync(0xffffffffu, bv, o);
                int   oi = __shfl_down_sync(0xffffffffu, bi, o);
                if (ov > bv || (ov == bv && oi < bi)) { bv = ov; bi = oi; }
            }
            bv = __shfl_sync(0xffffffffu, bv, 0);
            float e0 = (lane < NL) ? expf(v0 - bv) : 0.f;
            float e1 = (lane + 32 < NL) ? expf(v1 - bv) : 0.f;
            float ssum = e0 + e1;
#pragma unroll
            for (int o = 16; o; o >>= 1)
                ssum += __shfl_xor_sync(0xffffffffu, ssum, o);
            float inv = 1.f / ssum;
            if (lane < NL) s_wts[qi][lane] = e0 * inv;
            if (lane + 32 < NL) s_wts[qi][lane + 32] = e1 * inv;
            if (lane == 0 && (q0 + qi) < n_idx) out_idx[q0 + qi] = (float)bi;
        }
        __syncthreads();

        // ---- sampling: level weight folded into point weights; half2
        //      accumulation across ALL levels; one cross-lane reduce per qi.
        {
            int j = tid & 3;
            int slot = tid >> 2;             // 0..63
            int xc = j >> 1;
            int co = (j & 1) * 8;
            int h = slot & 7;                // loop-invariant head
            int warp = tid >> 5;
            const __half* basep = proj + h * (HW * HD) + co;

#pragma unroll 1
            for (int qi = 0; qi < QB; qi++) {
                float wxaw[4], offy[4];
                int cxl[4];
#pragma unroll
                for (int p = 0; p < 4; p++) {
                    int up = h * 4 + p;
                    wxaw[p] = s_wx[qi][up * 2 + xc] * s_aw[qi][up];
                    offy[p] = s_off[qi][up * 2 + 1];
                    cxl[p]  = s_cx[qi][up * 2 + xc];
                }
                __half2 ac0 = __float2half2_rn(0.f);
                __half2 ac1 = ac0, ac2 = ac0, ac3 = ac0;
                for (int u = slot; u < NL * NHEADS; u += 64) {
                    int l = u >> 3;
                    float ry = s_refy[qi][l];
                    float wl = s_wts[qi][l];
#pragma unroll
                    for (int p = 0; p < NPOINTS; p++) {
                        float py = (ry + offy[p]) * (float)HSP - 0.5f;
                        float y0f = floorf(py);
                        float dy = py - y0f;
                        int y0 = (int)y0f;
                        float wy0 = ((unsigned)y0 < HSP) ? (1.f - dy) : 0.f;
                        float wy1 = ((unsigned)(y0 + 1) < HSP) ? dy : 0.f;
                        int cy0 = min(max(y0, 0), HSP - 1);
                        int cy1 = min(max(y0 + 1, 0), HSP - 1);
                        uint4 v0 = *(const uint4*)(basep + (cy0 * WSP + cxl[p]) * HD);
                        uint4 v1 = *(const uint4*)(basep + (cy1 * WSP + cxl[p]) * HD);
                        float wlx = wxaw[p] * wl;
                        __half2 w0 = __float2half2_rn(wlx * wy0);
                        __half2 w1 = __float2half2_rn(wlx * wy1);
                        ac0 = __hfma2(*(__half2*)&v0.x, w0, ac0);
                        ac1 = __hfma2(*(__half2*)&v0.y, w0, ac1);
                        ac2 = __hfma2(*(__half2*)&v0.z, w0, ac2);
                        ac3 = __hfma2(*(__half2*)&v0.w, w0, ac3);
                        ac0 = __hfma2(*(__half2*)&v1.x, w1, ac0);
                        ac1 = __hfma2(*(__half2*)&v1.y, w1, ac1);
                        ac2 = __hfma2(*(__half2*)&v1.z, w1, ac2);
                        ac3 = __hfma2(*(__half2*)&v1.w, w1, ac3);
                    }
                }
                // one cross-lane reduce per qi (x-corner lanes j, j^2)
                unsigned t;
                t = __shfl_xor_sync(0xffffffffu, *(unsigned*)&ac0, 2);
                ac0 = __hadd2(ac0, *(__half2*)&t);
                t = __shfl_xor_sync(0xffffffffu, *(unsigned*)&ac1, 2);
                ac1 = __hadd2(ac1, *(__half2*)&t);
                t = __shfl_xor_sync(0xffffffffu, *(unsigned*)&ac2, 2);
                ac2 = __hadd2(ac2, *(__half2*)&t);
                t = __shfl_xor_sync(0xffffffffu, *(unsigned*)&ac3, 2);
                ac3 = __hadd2(ac3, *(__half2*)&t);
                if (j < 2) {
                    float2 f0 = __half22float2(ac0);
                    float2 f1 = __half22float2(ac1);
                    float2 f2 = __half22float2(ac2);
                    float2 f3 = __half22float2(ac3);
                    float4 w_;
                    w_.x = f0.x; w_.y = f0.y; w_.z = f1.x; w_.w = f1.y;
                    *(float4*)&s_pavg[warp][h * HD + co] = w_;
                    float4 w2_;
                    w2_.x = f2.x; w2_.y = f2.y; w2_.z = f3.x; w2_.w = f3.y;
                    *(float4*)&s_pavg[warp][h * HD + co + 4] = w2_;
                }
                __syncthreads();
                // reduce the 8 warp-partials for this qi
                if (tid < D) {
                    float acc = 0.f;
#pragma unroll
                    for (int w = 0; w < 8; w++)
                        acc += s_pavg[w][tid];
                    s_avg[qi][tid] = acc;
                }
                __syncthreads();
            }
        }

        // ---- final GEMV for ALL 8 queries, one W_out read (k-split)
        {
            int ch = tid & 127, half_ = tid >> 7;
            int k0 = half_ * 64;
            float a[QB];
#pragma unroll
            for (int qi = 0; qi < QB; qi++) a[qi] = 0.f;
#pragma unroll 4
            for (int k = 0; k < 64; k++) {
                float w = W_out[(k0 + k) * D + ch];
#pragma unroll
                for (int qi = 0; qi < QB; qi++)
                    a[qi] = fmaf(s_avg[qi][k0 + k], w, a[qi]);
            }
            if (half_) {
#pragma unroll
                for (int qi = 0; qi < QB; qi++) s_part[qi][ch] = a[qi];
            }
            __syncthreads();
            if (!half_) {
                float b = b_out[ch];
#pragma unroll
                for (int qi = 0; qi < QB; qi++)
                    out[(q0 + qi) * D + ch] =
                        a[qi] + s_part[qi][ch] + b + 2.0f * s_q[qi][ch];
            }
        }
    }
}

// ---------------------------------------------------------------------------
extern "C" void kernel_launch(void* const* d_in, const int* in_sizes, int n_in,
                              void* d_out, int out_size) {
    const float* query  = (const float*)d_in[0];
    const float* value  = (const float*)d_in[1];
    const float* refp   = (const float*)d_in[2];
    const float* W_off  = (const float*)d_in[3];
    const float* b_off  = (const float*)d_in[4];
    const float* W_attn = (const float*)d_in[5];
    const float* b_attn = (const float*)d_in[6];
    const float* W_val  = (const float*)d_in[7];
    const float* b_val  = (const float*)d_in[8];
    const float* W_out  = (const float*)d_in[9];
    const float* b_out  = (const float*)d_in[10];
    const float* W_proj = (const float*)d_in[11];
    // b_proj (d_in[12]) unused: constant shift is softmax/argmax-invariant.

    float* out = (float*)d_out;

    int n_idx = out_size - NQ * D;
    if (n_idx < 0) n_idx = 0;
    if (n_idx > NQ) n_idx = NQ;

    int tail_n = out_size - (NQ * D + NQ);
    float* tailp = out + NQ * D + NQ;
    if (tail_n < 0) { tail_n = 0; tailp = out; }

    fused_kernel<<<GRID, TPB>>>(query, value, refp, W_off, b_off,
                                W_attn, b_attn, W_val, b_val,
                                W_out, b_out, W_proj,
                                out, out + NQ * D, n_idx, tailp, tail_n);
}

// round 15
// speedup vs baseline: 1.8096x; 1.2499x over previous
#include <cuda_runtime.h>
#include <cuda_fp16.h>

#define NQ      10000
#define D       128
#define NHEADS  8
#define NPOINTS 4
#define HSP     51
#define WSP     102
#define HW      (HSP * WSP)
#define NL      50
#define HD      16
#define TPB     256
#define GRID    592
#define QB      8
#define RSTRIDE (52 * 32)            // halves per query in R table

// Scratch (device globals; no allocation allowed). Head-major table.
__device__ __align__(128) __half g_projh[NHEADS * HW * HD];  // fp16 1.33MB
__device__ float g_G[NHEADS * HW];    // fp32 scalar field [h][y*W+x]
__device__ unsigned g_arrive = 0;
__device__ unsigned g_depart = 0;
__device__ unsigned g_qctr = 0;       // work-stealing batch counter

extern __shared__ __align__(16) unsigned char dynsmem[];

// ---------------------------------------------------------------------------
__global__ void __launch_bounds__(TPB, 4)
fused_kernel(const float* __restrict__ query,
             const float* __restrict__ value,
             const float* __restrict__ ref,
             const float* __restrict__ W_off,
             const float* __restrict__ b_off,
             const float* __restrict__ W_attn,
             const float* __restrict__ b_attn,
             const float* __restrict__ W_val,
             const float* __restrict__ b_val,
             const float* __restrict__ W_out,
             const float* __restrict__ b_out,
             const float* __restrict__ W_proj,
             float* __restrict__ out,
             float* __restrict__ out_idx,
             int n_idx,
             float* __restrict__ tailp,
             int tail_n) {
    __half*  s_R    = (__half*)dynsmem;          // [QB][52][32] = 26.6 KB
    float*   s_part = (float*)dynsmem;           // alias: final-GEMV partials

    __shared__ __half2 s_pavg[2][64];     // 1 KB row-parity partials
    __shared__ float s_q[QB][D];
    __shared__ float s_avg[QB][D];
    __shared__ float s_off[QB][64];
    __shared__ float s_aw[QB][32];
    __shared__ float s_wp[D];
    __shared__ float s_wts[QB][64];
    __shared__ float s_refy[QB][NL];
    __shared__ float s_refx[QB];
    __shared__ float s_wx[QB][64];
    __shared__ int   s_cx[QB][64];
    __shared__ float s_lg[QB][NL];
    __shared__ float s_val[2 * D];
    __shared__ int   s_ylo[QB], s_yhi[QB];
    __shared__ int   s_qbase;

    const __half* __restrict__ proj = g_projh;
    int tid = threadIdx.x;

    // ===================== wp = W_out @ W_proj (needed in phase 0) ==========
    {
        if (tid < D) s_avg[0][tid] = W_proj[tid];
        __syncthreads();
        int warp = tid >> 5, lane = tid & 31;
        for (int r = warp; r < D; r += 8) {
            float a = 0.f;
#pragma unroll
            for (int kk = 0; kk < 4; kk++) {
                int k = lane + kk * 32;
                a = fmaf(W_out[r * D + k], s_avg[0][k], a);
            }
#pragma unroll
            for (int o = 16; o; o >>= 1)
                a += __shfl_down_sync(0xffffffffu, a, o);
            if (lane == 0) s_wp[r] = a;
        }
        __syncthreads();
    }

    // ===================== phase 0: value projection (fp32->fp16 + G) =======
    {
        if (blockIdx.x == 0 && tid == 0) g_qctr = 0;
        int ch = tid & 127;
        int half_ = tid >> 7;
        float wpc = s_wp[ch];
        for (int s0 = blockIdx.x * 2; s0 < HW; s0 += GRID * 2) {
            int s = s0 + half_;
            bool ok = s < HW;
            __syncthreads();
            if (ok) s_val[half_ * D + ch] = value[s * D + ch];
            __syncthreads();
            float acc = 0.f;
            if (ok) {
                acc = b_val[ch];
                const float* vr = &s_val[half_ * D];
#pragma unroll 8
                for (int k = 0; k < D; k++)
                    acc = fmaf(vr[k], W_val[k * D + ch], acc);
                g_projh[(ch >> 4) * (HW * HD) + s * HD + (ch & 15)] =
                    __float2half(acc);
            }
            float gterm = acc * wpc;
#pragma unroll
            for (int o = 1; o < 16; o <<= 1)
                gterm += __shfl_xor_sync(0xffffffffu, gterm, o);
            if (ok && (tid & 15) == 0)
                g_G[(ch >> 4) * HW + s] = gterm;
        }
        for (int i = blockIdx.x * TPB + tid; i < tail_n; i += GRID * TPB)
            tailp[i] = 0.f;
    }

    // ===================== device-wide barrier ==============================
    __syncthreads();
    if (tid == 0) {
        __threadfence();
        atomicAdd(&g_arrive, 1u);
        while (*(volatile unsigned*)&g_arrive < GRID) { }
        __threadfence();
        unsigned old = atomicAdd(&g_depart, 1u);
        if (old == GRID - 1) {
            *(volatile unsigned*)&g_arrive = 0u;
            __threadfence();
            *(volatile unsigned*)&g_depart = 0u;
        }
    }
    __syncthreads();

    // ===================== phase 1: work-stolen 8-query batches =============
    for (;;) {
        __syncthreads();
        if (tid == 0) s_qbase = (int)atomicAdd(&g_qctr, (unsigned)QB);
        __syncthreads();
        int q0 = s_qbase;
        if (q0 >= NQ) break;

        for (int i = tid; i < QB * D; i += TPB)
            s_q[i >> 7][i & 127] = query[q0 * D + i];
        __syncthreads();

        // ---- offsets (64) + attn logits (32) for ALL 8 queries, one W read
        if (tid < 192) {
            int col = tid >> 1;
            int half_ = tid & 1;
            bool is_off = col < 64;
            const float* W = is_off ? (W_off + col) : (W_attn + (col - 64));
            int stride = is_off ? 64 : 32;
            float b = 0.f;
            if (half_ == 0)
                b = is_off ? b_off[col] : b_attn[col - 64];
            float a[QB];
#pragma unroll
            for (int qi = 0; qi < QB; qi++) a[qi] = b;
            int k0 = half_ * 64;
#pragma unroll 4
            for (int k = 0; k < 64; k++) {
                float w = W[(k0 + k) * stride];
#pragma unroll
                for (int qi = 0; qi < QB; qi++)
                    a[qi] = fmaf(s_q[qi][k0 + k], w, a[qi]);
            }
#pragma unroll
            for (int qi = 0; qi < QB; qi++)
                a[qi] += __shfl_xor_sync(0xffffffffu, a[qi], 1);
            if (half_ == 0) {
                if (is_off) {
                    float nrm = (col & 1) ? (float)HSP : (float)WSP;
#pragma unroll
                    for (int qi = 0; qi < QB; qi++)
                        s_off[qi][col] = a[qi] / nrm;
                } else {
#pragma unroll
                    for (int qi = 0; qi < QB; qi++)
                        s_aw[qi][col - 64] = a[qi];
                }
            }
        } else {
            for (int i = tid - 192; i < QB * NL + QB; i += 64) {
                if (i < QB * NL) {
                    int qi = i / NL;
                    int l = i - qi * NL;
                    s_refy[qi][l] = ref[l * (NQ * 2) + (q0 + qi) * 2 + 1];
                } else {
                    int qi = i - QB * NL;
                    s_refx[qi] = ref[(q0 + qi) * 2];
                }
            }
        }
        __syncthreads();

        // ---- x precompute (all 256) then point softmax (tid<64)
        {
            int qi = tid >> 5, up = tid & 31;
            float px = (s_refx[qi] + s_off[qi][up * 2]) * (float)WSP - 0.5f;
            float x0f = floorf(px);
            float dx = px - x0f;
            int x0 = (int)x0f;
            s_wx[qi][up * 2 + 0] = ((unsigned)x0 < WSP) ? (1.f - dx) : 0.f;
            s_wx[qi][up * 2 + 1] = ((unsigned)(x0 + 1) < WSP) ? dx : 0.f;
            s_cx[qi][up * 2 + 0] = min(max(x0, 0), WSP - 1);
            s_cx[qi][up * 2 + 1] = min(max(x0 + 1, 0), WSP - 1);
        }
        if (tid < 64) {
            int qi = tid >> 3, h = tid & 7;
            float m = s_aw[qi][h * 4];
#pragma unroll
            for (int p = 1; p < 4; p++) m = fmaxf(m, s_aw[qi][h * 4 + p]);
            float e[4]; float ssum = 0.f;
#pragma unroll
            for (int p = 0; p < 4; p++) {
                e[p] = expf(s_aw[qi][h * 4 + p] - m);
                ssum += e[p];
            }
            float inv = 1.f / ssum;
#pragma unroll
            for (int p = 0; p < 4; p++) s_aw[qi][h * 4 + p] = e[p] * inv;
        }
        __syncthreads();

        // ---- exact fp32 level logits: warp = level, lane = (h,p)
        {
            int warp = tid >> 5, lane = tid & 31;
            int hh = lane >> 2;
            const float* Gh = g_G + hh * HW;
#pragma unroll 1
            for (int qi = 0; qi < QB; qi++) {
                float wx0 = s_wx[qi][lane * 2 + 0];
                float wx1 = s_wx[qi][lane * 2 + 1];
                int cx0 = s_cx[qi][lane * 2 + 0];
                int cx1 = s_cx[qi][lane * 2 + 1];
                float goffy = s_off[qi][lane * 2 + 1];
                float awl = s_aw[qi][lane];
                for (int l = warp; l < NL; l += 8) {
                    float py = (s_refy[qi][l] + goffy) * (float)HSP - 0.5f;
                    float y0f = floorf(py);
                    float dy = py - y0f;
                    int y0 = (int)y0f;
                    float wy0 = ((unsigned)y0 < HSP) ? (1.f - dy) : 0.f;
                    float wy1 = ((unsigned)(y0 + 1) < HSP) ? dy : 0.f;
                    int cy0 = min(max(y0, 0), HSP - 1);
                    int cy1 = min(max(y0 + 1, 0), HSP - 1);
                    const float* r0 = Gh + cy0 * WSP;
                    const float* r1 = Gh + cy1 * WSP;
                    float g00 = r0[cx0], g01 = r0[cx1];
                    float g10 = r1[cx0], g11 = r1[cx1];
                    float t = awl * (wy0 * fmaf(wx0, g00, wx1 * g01)
                                   + wy1 * fmaf(wx0, g10, wx1 * g11));
#pragma unroll
                    for (int o = 16; o; o >>= 1)
                        t += __shfl_xor_sync(0xffffffffu, t, o);
                    if (lane == 0) s_lg[qi][l] = t;
                }
            }
        }
        __syncthreads();

        // ---- level softmax + argmax: warps 0-7 (one per query)
        {
            int qi = tid >> 5, lane = tid & 31;
            float v0 = (lane < NL) ? s_lg[qi][lane] : -3.4e38f;
            float v1 = (lane + 32 < NL) ? s_lg[qi][lane + 32] : -3.4e38f;
            float bv; int bi;
            if (v1 > v0) { bv = v1; bi = lane + 32; }
            else         { bv = v0; bi = lane; }
#pragma unroll
            for (int o = 16; o; o >>= 1) {
                float ov = __shfl_down_sync(0xffffffffu, bv, o);
                int   oi = __shfl_down_sync(0xffffffffu, bi, o);
                if (ov > bv || (ov == bv && oi < bi)) { bv = ov; bi = oi; }
            }
            bv = __shfl_sync(0xffffffffu, bv, 0);
            float e0 = (lane < NL) ? expf(v0 - bv) : 0.f;
            float e1 = (lane + 32 < NL) ? expf(v1 - bv) : 0.f;
            float ssum = e0 + e1;
#pragma unroll
            for (int o = 16; o; o >>= 1)
                ssum += __shfl_xor_sync(0xffffffffu, ssum, o);
            float inv = 1.f / ssum;
            if (lane < NL) s_wts[qi][lane] = e0 * inv;
            if (lane + 32 < NL) s_wts[qi][lane + 32] = e1 * inv;
            if (lane == 0 && (q0 + qi) < n_idx) out_idx[q0 + qi] = (float)bi;
        }
        __syncthreads();

        // ---- build per-row weight table R[qi][y][up] = sum_l aw*wl*wy.
        //      One thread owns one (qi,up) column: deterministic, no races.
        {
            for (int i = tid; i < (QB * RSTRIDE) / 2; i += TPB)
                ((unsigned*)s_R)[i] = 0u;
            __syncthreads();
            int qi = tid >> 5;               // warp = query
            int up = tid & 31;
            float offy = s_off[qi][up * 2 + 1];
            float awl = s_aw[qi][up];
            __half* Rcol = s_R + qi * RSTRIDE + up;
            int ylo = 1000, yhi = -1000;
            for (int l = 0; l < NL; l++) {
                float wl = s_wts[qi][l] * awl;
                float py = (s_refy[qi][l] + offy) * (float)HSP - 0.5f;
                float y0f = floorf(py);
                float dy = py - y0f;
                int y0 = (int)y0f;
                if ((unsigned)y0 < HSP) {
                    __half* rp = Rcol + y0 * 32;
                    *rp = __float2half(__half2float(*rp) + wl * (1.f - dy));
                    ylo = min(ylo, y0); yhi = max(yhi, y0);
                }
                if ((unsigned)(y0 + 1) < HSP) {
                    __half* rp = Rcol + (y0 + 1) * 32;
                    *rp = __float2half(__half2float(*rp) + wl * dy);
                    ylo = min(ylo, y0 + 1); yhi = max(yhi, y0 + 1);
                }
            }
#pragma unroll
            for (int o = 16; o; o >>= 1) {
                ylo = min(ylo, __shfl_xor_sync(0xffffffffu, ylo, o));
                yhi = max(yhi, __shfl_xor_sync(0xffffffffu, yhi, o));
            }
            if ((tid & 31) == 0) { s_ylo[qi] = ylo; s_yhi[qi] = yhi; }
        }
        __syncthreads();

        // ---- row-factorized gather: thread = (rowparity, h, p, xc, co).
        //      Per distinct row: 1 LDS (R) + 1 LDG.128 + 4 HFMA2.
        {
            int rc = tid >> 7;               // row parity (warp-uniform)
            int l7 = tid & 127;
            int h = l7 >> 4, p = (l7 >> 2) & 3, xc = (l7 >> 1) & 1, co = l7 & 1;
            int up = h * 4 + p;
#pragma unroll 1
            for (int qi = 0; qi < QB; qi++) {
                int ylo = s_ylo[qi], yhi = s_yhi[qi];
                float coef = s_wx[qi][up * 2 + xc];
                int cxc = s_cx[qi][up * 2 + xc];
                const __half* base = proj + h * (HW * HD) + cxc * HD + co * 8;
                const __half* Rp = s_R + qi * RSTRIDE + up;
                __half2 a0 = __float2half2_rn(0.f);
                __half2 a1 = a0, a2 = a0, a3 = a0;
                for (int y = ylo + rc; y <= yhi; y += 2) {
                    float rw = coef * __half2float(Rp[y * 32]);
                    uint4 v = *(const uint4*)(base + y * (WSP * HD));
                    __half2 w = __float2half2_rn(rw);
                    a0 = __hfma2(*(__half2*)&v.x, w, a0);
                    a1 = __hfma2(*(__half2*)&v.y, w, a1);
                    a2 = __hfma2(*(__half2*)&v.z, w, a2);
                    a3 = __hfma2(*(__half2*)&v.w, w, a3);
                }
                // reduce over xc (xor2) and p (xor4, xor8)
                unsigned t;
#pragma unroll
                for (int o = 2; o <= 8; o <<= 1) {
                    t = __shfl_xor_sync(0xffffffffu, *(unsigned*)&a0, o);
                    a0 = __hadd2(a0, *(__half2*)&t);
                    t = __shfl_xor_sync(0xffffffffu, *(unsigned*)&a1, o);
                    a1 = __hadd2(a1, *(__half2*)&t);
                    t = __shfl_xor_sync(0xffffffffu, *(unsigned*)&a2, o);
                    a2 = __hadd2(a2, *(__half2*)&t);
                    t = __shfl_xor_sync(0xffffffffu, *(unsigned*)&a3, o);
                    a3 = __hadd2(a3, *(__half2*)&t);
                }
                if ((tid & 14) == 0) {       // lanes 0,1,16,17 of each warp
                    int lane = tid & 31;
                    int hh = ((tid >> 5) & 3) * 2 + (lane >> 4);
                    int coo = lane & 1;
                    __half2* dst = &s_pavg[rc][hh * 8 + coo * 4];
                    dst[0] = a0; dst[1] = a1; dst[2] = a2; dst[3] = a3;
                }
                __syncthreads();
                if (tid < 64) {
                    __half2 s = __hadd2(s_pavg[0][tid], s_pavg[1][tid]);
                    float2 f = __half22float2(s);
                    int hh = tid >> 3, rem = tid & 7;
                    int coo = rem >> 2, k = rem & 3;
                    int ch = hh * 16 + coo * 8 + k * 2;
                    s_avg[qi][ch] = f.x;
                    s_avg[qi][ch + 1] = f.y;
                }
                __syncthreads();
            }
        }

        // ---- final GEMV for ALL 8 queries, one W_out read (k-split).
        //      s_part aliases the R buffer (R is rebuilt next batch).
        {
            int ch = tid & 127, half_ = tid >> 7;
            int k0 = half_ * 64;
            float a[QB];
#pragma unroll
            for (int qi = 0; qi < QB; qi++) a[qi] = 0.f;
#pragma unroll 4
            for (int k = 0; k < 64; k++) {
                float w = W_out[(k0 + k) * D + ch];
#pragma unroll
                for (int qi = 0; qi < QB; qi++)
                    a[qi] = fmaf(s_avg[qi][k0 + k], w, a[qi]);
            }
            if (half_) {
#pragma unroll
                for (int qi = 0; qi < QB; qi++)
                    s_part[qi * D + ch] = a[qi];
            }
            __syncthreads();
            if (!half_) {
                float b = b_out[ch];
#pragma unroll
                for (int qi = 0; qi < QB; qi++)
                    out[(q0 + qi) * D + ch] =
                        a[qi] + s_part[qi * D + ch] + b + 2.0f * s_q[qi][ch];
            }
        }
    }
}

// ---------------------------------------------------------------------------
extern "C" void kernel_launch(void* const* d_in, const int* in_sizes, int n_in,
                              void* d_out, int out_size) {
    const float* query  = (const float*)d_in[0];
    const float* value  = (const float*)d_in[1];
    const float* refp   = (const float*)d_in[2];
    const float* W_off  = (const float*)d_in[3];
    const float* b_off  = (const float*)d_in[4];
    const float* W_attn = (const float*)d_in[5];
    const float* b_attn = (const float*)d_in[6];
    const float* W_val  = (const float*)d_in[7];
    const float* b_val  = (const float*)d_in[8];
    const float* W_out  = (const float*)d_in[9];
    const float* b_out  = (const float*)d_in[10];
    const float* W_proj = (const float*)d_in[11];
    // b_proj (d_in[12]) unused: constant shift is softmax/argmax-invariant.

    float* out = (float*)d_out;

    int n_idx = out_size - NQ * D;
    if (n_idx < 0) n_idx = 0;
    if (n_idx > NQ) n_idx = NQ;

    int tail_n = out_size - (NQ * D + NQ);
    float* tailp = out + NQ * D + NQ;
    if (tail_n < 0) { tail_n = 0; tailp = out; }

    size_t dyn = (size_t)QB * RSTRIDE * sizeof(__half);   // 26.6 KB
    cudaFuncSetAttribute(fused_kernel,
                         cudaFuncAttributeMaxDynamicSharedMemorySize, (int)dyn);

    fused_kernel<<<GRID, TPB, dyn>>>(query, value, refp, W_off, b_off,
                                     W_attn, b_attn, W_val, b_val,
                                     W_out, b_out, W_proj,
                                     out, out + NQ * D, n_idx, tailp, tail_n);
}

// round 16
// speedup vs baseline: 1.8721x; 1.0345x over previous
#include <cuda_runtime.h>
#include <cuda_fp16.h>

#define NQ      10000
#define D       128
#define NHEADS  8
#define NPOINTS 4
#define HSP     51
#define WSP     102
#define HW      (HSP * WSP)
#define NL      50
#define HD      16
#define TPB     256
#define GRID    592
#define QB      8
#define RSTRIDE (52 * 32)            // halves per query in R table

// Scratch (device globals; no allocation allowed). Head-major channel table;
// G field stored COLUMN-major [h][x*51+y] so column walks are contiguous.
__device__ __align__(128) __half g_projh[NHEADS * HW * HD];  // fp16 1.33MB
__device__ float g_G[NHEADS * HW];
__device__ unsigned g_arrive = 0;
__device__ unsigned g_depart = 0;
__device__ unsigned g_qctr = 0;       // work-stealing batch counter

extern __shared__ __align__(16) unsigned char dynsmem[];

// ---------------------------------------------------------------------------
__global__ void __launch_bounds__(TPB, 4)
fused_kernel(const float* __restrict__ query,
             const float* __restrict__ value,
             const float* __restrict__ ref,
             const float* __restrict__ W_off,
             const float* __restrict__ b_off,
             const float* __restrict__ W_attn,
             const float* __restrict__ b_attn,
             const float* __restrict__ W_val,
             const float* __restrict__ b_val,
             const float* __restrict__ W_out,
             const float* __restrict__ b_out,
             const float* __restrict__ W_proj,
             float* __restrict__ out,
             float* __restrict__ out_idx,
             int n_idx,
             float* __restrict__ tailp,
             int tail_n) {
    __half*  s_R    = (__half*)dynsmem;          // [QB][52][32] = 26.6 KB
    float*   s_part = (float*)dynsmem;           // alias: final-GEMV partials
    float*   s_gcol = (float*)dynsmem;           // alias: [32][53] combined G col

    __shared__ __half2 s_pavg[2][64];     // 1 KB row-parity partials
    __shared__ float s_q[QB][D];
    __shared__ float s_avg[QB][D];
    __shared__ float s_off[QB][64];
    __shared__ float s_aw[QB][32];
    __shared__ float s_wp[D];
    __shared__ float s_wts[QB][64];
    __shared__ float s_refy[QB][NL];
    __shared__ float s_refx[QB];
    __shared__ float s_wx[QB][64];
    __shared__ int   s_cx[QB][64];
    __shared__ float s_lg[QB][NL];
    __shared__ float s_val[2 * D];
    __shared__ int   s_ylo[QB], s_yhi[QB];
    __shared__ int   s_qbase;

    const __half* __restrict__ proj = g_projh;
    int tid = threadIdx.x;

    // ===================== wp = W_out @ W_proj (needed in phase 0) ==========
    {
        if (tid < D) s_avg[0][tid] = W_proj[tid];
        __syncthreads();
        int warp = tid >> 5, lane = tid & 31;
        for (int r = warp; r < D; r += 8) {
            float a = 0.f;
#pragma unroll
            for (int kk = 0; kk < 4; kk++) {
                int k = lane + kk * 32;
                a = fmaf(W_out[r * D + k], s_avg[0][k], a);
            }
#pragma unroll
            for (int o = 16; o; o >>= 1)
                a += __shfl_down_sync(0xffffffffu, a, o);
            if (lane == 0) s_wp[r] = a;
        }
        __syncthreads();
    }

    // ===================== phase 0: value projection (fp32->fp16 + G) =======
    {
        if (blockIdx.x == 0 && tid == 0) g_qctr = 0;
        int ch = tid & 127;
        int half_ = tid >> 7;
        float wpc = s_wp[ch];
        for (int s0 = blockIdx.x * 2; s0 < HW; s0 += GRID * 2) {
            int s = s0 + half_;
            bool ok = s < HW;
            __syncthreads();
            if (ok) s_val[half_ * D + ch] = value[s * D + ch];
            __syncthreads();
            float acc = 0.f;
            if (ok) {
                acc = b_val[ch];
                const float* vr = &s_val[half_ * D];
#pragma unroll 8
                for (int k = 0; k < D; k++)
                    acc = fmaf(vr[k], W_val[k * D + ch], acc);
                g_projh[(ch >> 4) * (HW * HD) + s * HD + (ch & 15)] =
                    __float2half(acc);
            }
            float gterm = acc * wpc;
#pragma unroll
            for (int o = 1; o < 16; o <<= 1)
                gterm += __shfl_xor_sync(0xffffffffu, gterm, o);
            if (ok && (tid & 15) == 0) {
                int yy = s / WSP;
                int xx = s - yy * WSP;
                g_G[(ch >> 4) * HW + xx * HSP + yy] = gterm;  // column-major
            }
        }
        for (int i = blockIdx.x * TPB + tid; i < tail_n; i += GRID * TPB)
            tailp[i] = 0.f;
    }

    // ===================== device-wide barrier ==============================
    __syncthreads();
    if (tid == 0) {
        __threadfence();
        atomicAdd(&g_arrive, 1u);
        while (*(volatile unsigned*)&g_arrive < GRID) { }
        __threadfence();
        unsigned old = atomicAdd(&g_depart, 1u);
        if (old == GRID - 1) {
            *(volatile unsigned*)&g_arrive = 0u;
            __threadfence();
            *(volatile unsigned*)&g_depart = 0u;
        }
    }
    __syncthreads();

    // ===================== phase 1: work-stolen 8-query batches =============
    for (;;) {
        __syncthreads();
        if (tid == 0) s_qbase = (int)atomicAdd(&g_qctr, (unsigned)QB);
        __syncthreads();
        int q0 = s_qbase;
        if (q0 >= NQ) break;

        for (int i = tid; i < QB * D; i += TPB)
            s_q[i >> 7][i & 127] = query[q0 * D + i];
        __syncthreads();

        // ---- offsets (64) + attn logits (32) for ALL 8 queries, one W read
        if (tid < 192) {
            int col = tid >> 1;
            int half_ = tid & 1;
            bool is_off = col < 64;
            const float* W = is_off ? (W_off + col) : (W_attn + (col - 64));
            int stride = is_off ? 64 : 32;
            float b = 0.f;
            if (half_ == 0)
                b = is_off ? b_off[col] : b_attn[col - 64];
            float a[QB];
#pragma unroll
            for (int qi = 0; qi < QB; qi++) a[qi] = b;
            int k0 = half_ * 64;
#pragma unroll 4
            for (int k = 0; k < 64; k++) {
                float w = W[(k0 + k) * stride];
#pragma unroll
                for (int qi = 0; qi < QB; qi++)
                    a[qi] = fmaf(s_q[qi][k0 + k], w, a[qi]);
            }
#pragma unroll
            for (int qi = 0; qi < QB; qi++)
                a[qi] += __shfl_xor_sync(0xffffffffu, a[qi], 1);
            if (half_ == 0) {
                if (is_off) {
                    float nrm = (col & 1) ? (float)HSP : (float)WSP;
#pragma unroll
                    for (int qi = 0; qi < QB; qi++)
                        s_off[qi][col] = a[qi] / nrm;
                } else {
#pragma unroll
                    for (int qi = 0; qi < QB; qi++)
                        s_aw[qi][col - 64] = a[qi];
                }
            }
        } else {
            for (int i = tid - 192; i < QB * NL + QB; i += 64) {
                if (i < QB * NL) {
                    int qi = i / NL;
                    int l = i - qi * NL;
                    s_refy[qi][l] = ref[l * (NQ * 2) + (q0 + qi) * 2 + 1];
                } else {
                    int qi = i - QB * NL;
                    s_refx[qi] = ref[(q0 + qi) * 2];
                }
            }
        }
        __syncthreads();

        // ---- x precompute (all 256) then point softmax (tid<64)
        {
            int qi = tid >> 5, up = tid & 31;
            float px = (s_refx[qi] + s_off[qi][up * 2]) * (float)WSP - 0.5f;
            float x0f = floorf(px);
            float dx = px - x0f;
            int x0 = (int)x0f;
            s_wx[qi][up * 2 + 0] = ((unsigned)x0 < WSP) ? (1.f - dx) : 0.f;
            s_wx[qi][up * 2 + 1] = ((unsigned)(x0 + 1) < WSP) ? dx : 0.f;
            s_cx[qi][up * 2 + 0] = min(max(x0, 0), WSP - 1);
            s_cx[qi][up * 2 + 1] = min(max(x0 + 1, 0), WSP - 1);
        }
        if (tid < 64) {
            int qi = tid >> 3, h = tid & 7;
            float m = s_aw[qi][h * 4];
#pragma unroll
            for (int p = 1; p < 4; p++) m = fmaxf(m, s_aw[qi][h * 4 + p]);
            float e[4]; float ssum = 0.f;
#pragma unroll
            for (int p = 0; p < 4; p++) {
                e[p] = expf(s_aw[qi][h * 4 + p] - m);
                ssum += e[p];
            }
            float inv = 1.f / ssum;
#pragma unroll
            for (int p = 0; p < 4; p++) s_aw[qi][h * 4 + p] = e[p] * inv;
        }
        __syncthreads();

        // ---- exact fp32 level logits via per-query combined G columns.
        //      Gcol[up][y] = fmaf(wx0, G[cx0][y], wx1*G[cx1][y]) — identical
        //      fp32 term as before, computed once per y instead of per level.
        for (int qi = 0; qi < QB; qi++) {
            {   // fill combined columns (coalesced: y contiguous, col-major G)
                int up = tid >> 3, yb = tid & 7;
                float wx0 = s_wx[qi][up * 2 + 0];
                float wx1 = s_wx[qi][up * 2 + 1];
                const float* c0 = g_G + (up >> 2) * HW + s_cx[qi][up * 2 + 0] * HSP;
                const float* c1 = g_G + (up >> 2) * HW + s_cx[qi][up * 2 + 1] * HSP;
                for (int y = yb; y < HSP; y += 8)
                    s_gcol[up * 53 + y] = fmaf(wx0, c0[y], wx1 * c1[y]);
            }
            __syncthreads();
            {   // logits: warp = level, lane = (h,p); reads smem only
                int warp = tid >> 5, lane = tid & 31;
                float goffy = s_off[qi][lane * 2 + 1];
                float awl = s_aw[qi][lane];
                const float* Gc = s_gcol + lane * 53;
                for (int l = warp; l < NL; l += 8) {
                    float py = (s_refy[qi][l] + goffy) * (float)HSP - 0.5f;
                    float y0f = floorf(py);
                    float dy = py - y0f;
                    int y0 = (int)y0f;
                    float wy0 = ((unsigned)y0 < HSP) ? (1.f - dy) : 0.f;
                    float wy1 = ((unsigned)(y0 + 1) < HSP) ? dy : 0.f;
                    int cy0 = min(max(y0, 0), HSP - 1);
                    int cy1 = min(max(y0 + 1, 0), HSP - 1);
                    float t = awl * (wy0 * Gc[cy0] + wy1 * Gc[cy1]);
#pragma unroll
                    for (int o = 16; o; o >>= 1)
                        t += __shfl_xor_sync(0xffffffffu, t, o);
                    if (lane == 0) s_lg[qi][l] = t;
                }
            }
            __syncthreads();
        }

        // ---- level softmax + argmax: warps 0-7 (one per query)
        {
            int qi = tid >> 5, lane = tid & 31;
            float v0 = (lane < NL) ? s_lg[qi][lane] : -3.4e38f;
            float v1 = (lane + 32 < NL) ? s_lg[qi][lane + 32] : -3.4e38f;
            float bv; int bi;
            if (v1 > v0) { bv = v1; bi = lane + 32; }
            else         { bv = v0; bi = lane; }
#pragma unroll
            for (int o = 16; o; o >>= 1) {
                float ov = __shfl_down_sync(0xffffffffu, bv, o);
                int   oi = __shfl_down_sync(0xffffffffu, bi, o);
                if (ov > bv || (ov == bv && oi < bi)) { bv = ov; bi = oi; }
            }
            bv = __shfl_sync(0xffffffffu, bv, 0);
            float e0 = (lane < NL) ? expf(v0 - bv) : 0.f;
            float e1 = (lane + 32 < NL) ? expf(v1 - bv) : 0.f;
            float ssum = e0 + e1;
#pragma unroll
            for (int o = 16; o; o >>= 1)
                ssum += __shfl_xor_sync(0xffffffffu, ssum, o);
            float inv = 1.f / ssum;
            if (lane < NL) s_wts[qi][lane] = e0 * inv;
            if (lane + 32 < NL) s_wts[qi][lane + 32] = e1 * inv;
            if (lane == 0 && (q0 + qi) < n_idx) out_idx[q0 + qi] = (float)bi;
        }
        __syncthreads();

        // ---- build per-row weight table R[qi][y][up] = sum_l aw*wl*wy.
        {
            for (int i = tid; i < (QB * RSTRIDE) / 2; i += TPB)
                ((unsigned*)s_R)[i] = 0u;
            __syncthreads();
            int qi = tid >> 5;               // warp = query
            int up = tid & 31;
            float offy = s_off[qi][up * 2 + 1];
            float awl = s_aw[qi][up];
            __half* Rcol = s_R + qi * RSTRIDE + up;
            int ylo = 1000, yhi = -1000;
            for (int l = 0; l < NL; l++) {
                float wl = s_wts[qi][l] * awl;
                float py = (s_refy[qi][l] + offy) * (float)HSP - 0.5f;
                float y0f = floorf(py);
                float dy = py - y0f;
                int y0 = (int)y0f;
                if ((unsigned)y0 < HSP) {
                    __half* rp = Rcol + y0 * 32;
                    *rp = __float2half(__half2float(*rp) + wl * (1.f - dy));
                    ylo = min(ylo, y0); yhi = max(yhi, y0);
                }
                if ((unsigned)(y0 + 1) < HSP) {
                    __half* rp = Rcol + (y0 + 1) * 32;
                    *rp = __float2half(__half2float(*rp) + wl * dy);
                    ylo = min(ylo, y0 + 1); yhi = max(yhi, y0 + 1);
                }
            }
#pragma unroll
            for (int o = 16; o; o >>= 1) {
                ylo = min(ylo, __shfl_xor_sync(0xffffffffu, ylo, o));
                yhi = max(yhi, __shfl_xor_sync(0xffffffffu, yhi, o));
            }
            if ((tid & 31) == 0) { s_ylo[qi] = ylo; s_yhi[qi] = yhi; }
        }
        __syncthreads();

        // ---- row-factorized gather: thread = (rowparity, h, p, xc, co).
        {
            int rc = tid >> 7;               // row parity (warp-uniform)
            int l7 = tid & 127;
            int h = l7 >> 4, p = (l7 >> 2) & 3, xc = (l7 >> 1) & 1, co = l7 & 1;
            int up = h * 4 + p;
#pragma unroll 1
            for (int qi = 0; qi < QB; qi++) {
                int ylo = s_ylo[qi], yhi = s_yhi[qi];
                float coef = s_wx[qi][up * 2 + xc];
                int cxc = s_cx[qi][up * 2 + xc];
                const __half* base = proj + h * (HW * HD) + cxc * HD + co * 8;
                const __half* Rp = s_R + qi * RSTRIDE + up;
                __half2 a0 = __float2half2_rn(0.f);
                __half2 a1 = a0, a2 = a0, a3 = a0;
                for (int y = ylo + rc; y <= yhi; y += 2) {
                    float rw = coef * __half2float(Rp[y * 32]);
                    uint4 v = *(const uint4*)(base + y * (WSP * HD));
                    __half2 w = __float2half2_rn(rw);
                    a0 = __hfma2(*(__half2*)&v.x, w, a0);
                    a1 = __hfma2(*(__half2*)&v.y, w, a1);
                    a2 = __hfma2(*(__half2*)&v.z, w, a2);
                    a3 = __hfma2(*(__half2*)&v.w, w, a3);
                }
                // reduce over xc (xor2) and p (xor4, xor8)
                unsigned t;
#pragma unroll
                for (int o = 2; o <= 8; o <<= 1) {
                    t = __shfl_xor_sync(0xffffffffu, *(unsigned*)&a0, o);
                    a0 = __hadd2(a0, *(__half2*)&t);
                    t = __shfl_xor_sync(0xffffffffu, *(unsigned*)&a1, o);
                    a1 = __hadd2(a1, *(__half2*)&t);
                    t = __shfl_xor_sync(0xffffffffu, *(unsigned*)&a2, o);
                    a2 = __hadd2(a2, *(__half2*)&t);
                    t = __shfl_xor_sync(0xffffffffu, *(unsigned*)&a3, o);
                    a3 = __hadd2(a3, *(__half2*)&t);
                }
                if ((tid & 14) == 0) {       // lanes 0,1,16,17 of each warp
                    int lane = tid & 31;
                    int hh = ((tid >> 5) & 3) * 2 + (lane >> 4);
                    int coo = lane & 1;
                    __half2* dst = &s_pavg[rc][hh * 8 + coo * 4];
                    dst[0] = a0; dst[1] = a1; dst[2] = a2; dst[3] = a3;
                }
                __syncthreads();
                if (tid < 64) {
                    __half2 s = __hadd2(s_pavg[0][tid], s_pavg[1][tid]);
                    float2 f = __half22float2(s);
                    int hh = tid >> 3, rem = tid & 7;
                    int coo = rem >> 2, k = rem & 3;
                    int ch = hh * 16 + coo * 8 + k * 2;
                    s_avg[qi][ch] = f.x;
                    s_avg[qi][ch + 1] = f.y;
                }
                __syncthreads();
            }
        }

        // ---- final GEMV for ALL 8 queries, one W_out read (k-split).
        //      s_part aliases the R buffer (R is rebuilt next batch).
        {
            int ch = tid & 127, half_ = tid >> 7;
            int k0 = half_ * 64;
            float a[QB];
#pragma unroll
            for (int qi = 0; qi < QB; qi++) a[qi] = 0.f;
#pragma unroll 4
            for (int k = 0; k < 64; k++) {
                float w = W_out[(k0 + k) * D + ch];
#pragma unroll
                for (int qi = 0; qi < QB; qi++)
                    a[qi] = fmaf(s_avg[qi][k0 + k], w, a[qi]);
            }
            if (half_) {
#pragma unroll
                for (int qi = 0; qi < QB; qi++)
                    s_part[qi * D + ch] = a[qi];
            }
            __syncthreads();
            if (!half_) {
                float b = b_out[ch];
#pragma unroll
                for (int qi = 0; qi < QB; qi++)
                    out[(q0 + qi) * D + ch] =
                        a[qi] + s_part[qi * D + ch] + b + 2.0f * s_q[qi][ch];
            }
        }
    }
}

// ---------------------------------------------------------------------------
extern "C" void kernel_launch(void* const* d_in, const int* in_sizes, int n_in,
                              void* d_out, int out_size) {
    const float* query  = (const float*)d_in[0];
    const float* value  = (const float*)d_in[1];
    const float* refp   = (const float*)d_in[2];
    const float* W_off  = (const float*)d_in[3];
    const float* b_off  = (const float*)d_in[4];
    const float* W_attn = (const float*)d_in[5];
    const float* b_attn = (const float*)d_in[6];
    const float* W_val  = (const float*)d_in[7];
    const float* b_val  = (const float*)d_in[8];
    const float* W_out  = (const float*)d_in[9];
    const float* b_out  = (const float*)d_in[10];
    const float* W_proj = (const float*)d_in[11];
    // b_proj (d_in[12]) unused: constant shift is softmax/argmax-invariant.

    float* out = (float*)d_out;

    int n_idx = out_size - NQ * D;
    if (n_idx < 0) n_idx = 0;
    if (n_idx > NQ) n_idx = NQ;

    int tail_n = out_size - (NQ * D + NQ);
    float* tailp = out + NQ * D + NQ;
    if (tail_n < 0) { tail_n = 0; tailp = out; }

    size_t dyn = (size_t)QB * RSTRIDE * sizeof(__half);   // 26.6 KB
    cudaFuncSetAttribute(fused_kernel,
                         cudaFuncAttributeMaxDynamicSharedMemorySize, (int)dyn);

    fused_kernel<<<GRID, TPB, dyn>>>(query, value, refp, W_off, b_off,
                                     W_attn, b_attn, W_val, b_val,
                                     W_out, b_out, W_proj,
                                     out, out + NQ * D, n_idx, tailp, tail_n);
}

// round 17
// speedup vs baseline: 1.9599x; 1.0469x over previous
#include <cuda_runtime.h>
#include <cuda_fp16.h>

#define NQ      10000
#define D       128
#define NHEADS  8
#define NPOINTS 4
#define HSP     51
#define WSP     102
#define HW      (HSP * WSP)
#define NL      50
#define HD      16
#define TPB     256
#define GRID    592
#define QB      8
#define RSTRIDE (52 * 32)            // halves per query in R table
#define GCSTRIDE (32 * 53)           // floats per query in Gcol buffer

// Scratch (device globals; no allocation allowed). Head-major channel table;
// G field stored COLUMN-major [h][x*51+y] so column walks are contiguous.
__device__ __align__(128) __half g_projh[NHEADS * HW * HD];  // fp16 1.33MB
__device__ float g_G[NHEADS * HW];
__device__ unsigned g_arrive = 0;
__device__ unsigned g_depart = 0;
__device__ unsigned g_qctr = 0;       // work-stealing batch counter

extern __shared__ __align__(16) unsigned char dynsmem[];

// ---------------------------------------------------------------------------
__global__ void __launch_bounds__(TPB, 4)
fused_kernel(const float* __restrict__ query,
             const float* __restrict__ value,
             const float* __restrict__ ref,
             const float* __restrict__ W_off,
             const float* __restrict__ b_off,
             const float* __restrict__ W_attn,
             const float* __restrict__ b_attn,
             const float* __restrict__ W_val,
             const float* __restrict__ b_val,
             const float* __restrict__ W_out,
             const float* __restrict__ b_out,
             const float* __restrict__ W_proj,
             float* __restrict__ out,
             float* __restrict__ out_idx,
             int n_idx,
             float* __restrict__ tailp,
             int tail_n) {
    __half*  s_R    = (__half*)dynsmem;          // [QB][52][32] = 26.6 KB
    float*   s_part = (float*)dynsmem;           // alias: final-GEMV partials
    float*   s_gcol = (float*)dynsmem;           // alias: [4][32][53] G columns

    __shared__ __half2 s_pavg[QB][2][64];  // 4 KB all-qi row-parity partials
    __shared__ float s_q[QB][D];
    __shared__ float s_avg[QB][D];
    __shared__ float s_off[QB][64];
    __shared__ float s_aw[QB][32];
    __shared__ float s_wp[D];
    __shared__ float s_wts[QB][64];
    __shared__ float s_refy[QB][NL];
    __shared__ float s_refx[QB];
    __shared__ float s_wx[QB][64];
    __shared__ int   s_cx[QB][64];
    __shared__ float s_lg[QB][NL];
    __shared__ float s_val[2 * D];
    __shared__ int   s_ylo[QB], s_yhi[QB];
    __shared__ int   s_qbase;

    const __half* __restrict__ proj = g_projh;
    int tid = threadIdx.x;

    // ===================== wp = W_out @ W_proj (needed in phase 0) ==========
    {
        if (tid < D) s_avg[0][tid] = W_proj[tid];
        __syncthreads();
        int warp = tid >> 5, lane = tid & 31;
        for (int r = warp; r < D; r += 8) {
            float a = 0.f;
#pragma unroll
            for (int kk = 0; kk < 4; kk++) {
                int k = lane + kk * 32;
                a = fmaf(W_out[r * D + k], s_avg[0][k], a);
            }
#pragma unroll
            for (int o = 16; o; o >>= 1)
                a += __shfl_down_sync(0xffffffffu, a, o);
            if (lane == 0) s_wp[r] = a;
        }
        __syncthreads();
    }

    // ===================== phase 0: value projection (fp32->fp16 + G) =======
    {
        if (blockIdx.x == 0 && tid == 0) g_qctr = 0;
        int ch = tid & 127;
        int half_ = tid >> 7;
        float wpc = s_wp[ch];
        for (int s0 = blockIdx.x * 2; s0 < HW; s0 += GRID * 2) {
            int s = s0 + half_;
            bool ok = s < HW;
            __syncthreads();
            if (ok) s_val[half_ * D + ch] = value[s * D + ch];
            __syncthreads();
            float acc = 0.f;
            if (ok) {
                acc = b_val[ch];
                const float* vr = &s_val[half_ * D];
#pragma unroll 8
                for (int k = 0; k < D; k++)
                    acc = fmaf(vr[k], W_val[k * D + ch], acc);
                g_projh[(ch >> 4) * (HW * HD) + s * HD + (ch & 15)] =
                    __float2half(acc);
            }
            float gterm = acc * wpc;
#pragma unroll
            for (int o = 1; o < 16; o <<= 1)
                gterm += __shfl_xor_sync(0xffffffffu, gterm, o);
            if (ok && (tid & 15) == 0) {
                int yy = s / WSP;
                int xx = s - yy * WSP;
                g_G[(ch >> 4) * HW + xx * HSP + yy] = gterm;  // column-major
            }
        }
        for (int i = blockIdx.x * TPB + tid; i < tail_n; i += GRID * TPB)
            tailp[i] = 0.f;
    }

    // ===================== device-wide barrier ==============================
    __syncthreads();
    if (tid == 0) {
        __threadfence();
        atomicAdd(&g_arrive, 1u);
        while (*(volatile unsigned*)&g_arrive < GRID) { }
        __threadfence();
        unsigned old = atomicAdd(&g_depart, 1u);
        if (old == GRID - 1) {
            *(volatile unsigned*)&g_arrive = 0u;
            __threadfence();
            *(volatile unsigned*)&g_depart = 0u;
        }
    }
    __syncthreads();

    // ===================== phase 1: work-stolen 8-query batches =============
    for (;;) {
        __syncthreads();
        if (tid == 0) s_qbase = (int)atomicAdd(&g_qctr, (unsigned)QB);
        __syncthreads();
        int q0 = s_qbase;
        if (q0 >= NQ) break;

        for (int i = tid; i < QB * D; i += TPB)
            s_q[i >> 7][i & 127] = query[q0 * D + i];
        __syncthreads();

        // ---- offsets (64) + attn logits (32) for ALL 8 queries, one W read
        if (tid < 192) {
            int col = tid >> 1;
            int half_ = tid & 1;
            bool is_off = col < 64;
            const float* W = is_off ? (W_off + col) : (W_attn + (col - 64));
            int stride = is_off ? 64 : 32;
            float b = 0.f;
            if (half_ == 0)
                b = is_off ? b_off[col] : b_attn[col - 64];
            float a[QB];
#pragma unroll
            for (int qi = 0; qi < QB; qi++) a[qi] = b;
            int k0 = half_ * 64;
#pragma unroll 4
            for (int k = 0; k < 64; k++) {
                float w = W[(k0 + k) * stride];
#pragma unroll
                for (int qi = 0; qi < QB; qi++)
                    a[qi] = fmaf(s_q[qi][k0 + k], w, a[qi]);
            }
#pragma unroll
            for (int qi = 0; qi < QB; qi++)
                a[qi] += __shfl_xor_sync(0xffffffffu, a[qi], 1);
            if (half_ == 0) {
                if (is_off) {
                    float nrm = (col & 1) ? (float)HSP : (float)WSP;
#pragma unroll
                    for (int qi = 0; qi < QB; qi++)
                        s_off[qi][col] = a[qi] / nrm;
                } else {
#pragma unroll
                    for (int qi = 0; qi < QB; qi++)
                        s_aw[qi][col - 64] = a[qi];
                }
            }
        } else {
            for (int i = tid - 192; i < QB * NL + QB; i += 64) {
                if (i < QB * NL) {
                    int qi = i / NL;
                    int l = i - qi * NL;
                    s_refy[qi][l] = ref[l * (NQ * 2) + (q0 + qi) * 2 + 1];
                } else {
                    int qi = i - QB * NL;
                    s_refx[qi] = ref[(q0 + qi) * 2];
                }
            }
        }
        __syncthreads();

        // ---- x precompute (all 256) then point softmax (tid<64)
        {
            int qi = tid >> 5, up = tid & 31;
            float px = (s_refx[qi] + s_off[qi][up * 2]) * (float)WSP - 0.5f;
            float x0f = floorf(px);
            float dx = px - x0f;
            int x0 = (int)x0f;
            s_wx[qi][up * 2 + 0] = ((unsigned)x0 < WSP) ? (1.f - dx) : 0.f;
            s_wx[qi][up * 2 + 1] = ((unsigned)(x0 + 1) < WSP) ? dx : 0.f;
            s_cx[qi][up * 2 + 0] = min(max(x0, 0), WSP - 1);
            s_cx[qi][up * 2 + 1] = min(max(x0 + 1, 0), WSP - 1);
        }
        if (tid < 64) {
            int qi = tid >> 3, h = tid & 7;
            float m = s_aw[qi][h * 4];
#pragma unroll
            for (int p = 1; p < 4; p++) m = fmaxf(m, s_aw[qi][h * 4 + p]);
            float e[4]; float ssum = 0.f;
#pragma unroll
            for (int p = 0; p < 4; p++) {
                e[p] = expf(s_aw[qi][h * 4 + p] - m);
                ssum += e[p];
            }
            float inv = 1.f / ssum;
#pragma unroll
            for (int p = 0; p < 4; p++) s_aw[qi][h * 4 + p] = e[p] * inv;
        }
        __syncthreads();

        // ---- exact fp32 level logits via combined G columns, 4 queries/pass
        for (int pass = 0; pass < 2; pass++) {
            {   // fill 4 queries' combined columns (y contiguous, col-major G)
                int qi2 = tid >> 6;
                int rem = tid & 63;
                int up = rem >> 1, yb = rem & 1;
                int qi = pass * 4 + qi2;
                float wx0 = s_wx[qi][up * 2 + 0];
                float wx1 = s_wx[qi][up * 2 + 1];
                const float* c0 = g_G + (up >> 2) * HW + s_cx[qi][up * 2 + 0] * HSP;
                const float* c1 = g_G + (up >> 2) * HW + s_cx[qi][up * 2 + 1] * HSP;
                float* gc = s_gcol + qi2 * GCSTRIDE + up * 53;
                for (int y = yb; y < HSP; y += 2)
                    gc[y] = fmaf(wx0, c0[y], wx1 * c1[y]);
            }
            __syncthreads();
            {   // logits: warp = level, lane = (h,p); smem reads only
                int warp = tid >> 5, lane = tid & 31;
                for (int qi2 = 0; qi2 < 4; qi2++) {
                    int qi = pass * 4 + qi2;
                    float goffy = s_off[qi][lane * 2 + 1];
                    float awl = s_aw[qi][lane];
                    const float* Gc = s_gcol + qi2 * GCSTRIDE + lane * 53;
                    for (int l = warp; l < NL; l += 8) {
                        float py = (s_refy[qi][l] + goffy) * (float)HSP - 0.5f;
                        float y0f = floorf(py);
                        float dy = py - y0f;
                        int y0 = (int)y0f;
                        float wy0 = ((unsigned)y0 < HSP) ? (1.f - dy) : 0.f;
                        float wy1 = ((unsigned)(y0 + 1) < HSP) ? dy : 0.f;
                        int cy0 = min(max(y0, 0), HSP - 1);
                        int cy1 = min(max(y0 + 1, 0), HSP - 1);
                        float t = awl * (wy0 * Gc[cy0] + wy1 * Gc[cy1]);
#pragma unroll
                        for (int o = 16; o; o >>= 1)
                            t += __shfl_xor_sync(0xffffffffu, t, o);
                        if (lane == 0) s_lg[qi][l] = t;
                    }
                }
            }
            __syncthreads();
        }

        // ---- level softmax + argmax: warps 0-7 (one per query)
        {
            int qi = tid >> 5, lane = tid & 31;
            float v0 = (lane < NL) ? s_lg[qi][lane] : -3.4e38f;
            float v1 = (lane + 32 < NL) ? s_lg[qi][lane + 32] : -3.4e38f;
            float bv; int bi;
            if (v1 > v0) { bv = v1; bi = lane + 32; }
            else         { bv = v0; bi = lane; }
#pragma unroll
            for (int o = 16; o; o >>= 1) {
                float ov = __shfl_down_sync(0xffffffffu, bv, o);
                int   oi = __shfl_down_sync(0xffffffffu, bi, o);
                if (ov > bv || (ov == bv && oi < bi)) { bv = ov; bi = oi; }
            }
            bv = __shfl_sync(0xffffffffu, bv, 0);
            float e0 = (lane < NL) ? expf(v0 - bv) : 0.f;
            float e1 = (lane + 32 < NL) ? expf(v1 - bv) : 0.f;
            float ssum = e0 + e1;
#pragma unroll
            for (int o = 16; o; o >>= 1)
                ssum += __shfl_xor_sync(0xffffffffu, ssum, o);
            float inv = 1.f / ssum;
            if (lane < NL) s_wts[qi][lane] = e0 * inv;
            if (lane + 32 < NL) s_wts[qi][lane + 32] = e1 * inv;
            if (lane == 0 && (q0 + qi) < n_idx) out_idx[q0 + qi] = (float)bi;
        }
        __syncthreads();

        // ---- build R[qi][y][up] = sum_l aw*wl*wy via register window.
        //      py is strictly monotonic in l (theta monotonic in z), so y0 is
        //      non-increasing: each row is flushed once (fp32 accumulate, one
        //      fp16 round). Multi-step jumps / first iter use safe RMW.
        {
            for (int i = tid; i < (QB * RSTRIDE) / 2; i += TPB)
                ((unsigned*)s_R)[i] = 0u;
            __syncthreads();
            int qi = tid >> 5;               // warp = query
            int up = tid & 31;
            float offy = s_off[qi][up * 2 + 1];
            float awl = s_aw[qi][up];
            __half* Rcol = s_R + qi * RSTRIDE + up;
            int ylo = 1000, yhi = -1000;
            float accLo = 0.f, accHi = 0.f;
            int ycur = -100000;
            for (int l = 0; l < NL; l++) {
                float wl = s_wts[qi][l] * awl;
                float py = (s_refy[qi][l] + offy) * (float)HSP - 0.5f;
                float y0f = floorf(py);
                float dy = py - y0f;
                int y0 = (int)y0f;
                float c0 = ((unsigned)y0 < HSP) ? wl * (1.f - dy) : 0.f;
                float c1 = ((unsigned)(y0 + 1) < HSP) ? wl * dy : 0.f;
                if ((unsigned)y0 < HSP) { ylo = min(ylo, y0); yhi = max(yhi, y0); }
                if ((unsigned)(y0 + 1) < HSP) { ylo = min(ylo, y0 + 1); yhi = max(yhi, y0 + 1); }
                if (y0 == ycur) {
                    accLo += c0; accHi += c1;
                } else if (y0 == ycur - 1) {
                    if ((unsigned)(ycur + 1) < HSP)
                        Rcol[(ycur + 1) * 32] = __float2half(accHi);
                    accHi = accLo + c1; accLo = c0; ycur = y0;
                } else if (y0 == ycur + 1) {
                    if ((unsigned)ycur < HSP)
                        Rcol[ycur * 32] = __float2half(accLo);
                    accLo = accHi + c0; accHi = c1; ycur = y0;
                } else {
                    if ((unsigned)ycur < HSP) {
                        __half* rp = Rcol + ycur * 32;
                        *rp = __float2half(__half2float(*rp) + accLo);
                    }
                    if ((unsigned)(ycur + 1) < HSP) {
                        __half* rp = Rcol + (ycur + 1) * 32;
                        *rp = __float2half(__half2float(*rp) + accHi);
                    }
                    accLo = c0; accHi = c1;
                    if ((unsigned)y0 < HSP)
                        accLo += __half2float(Rcol[y0 * 32]);
                    if ((unsigned)(y0 + 1) < HSP)
                        accHi += __half2float(Rcol[(y0 + 1) * 32]);
                    ycur = y0;
                }
            }
            if ((unsigned)ycur < HSP) {
                __half* rp = Rcol + ycur * 32;
                *rp = __float2half(__half2float(*rp) + accLo);
            }
            if ((unsigned)(ycur + 1) < HSP) {
                __half* rp = Rcol + (ycur + 1) * 32;
                *rp = __float2half(__half2float(*rp) + accHi);
            }
#pragma unroll
            for (int o = 16; o; o >>= 1) {
                ylo = min(ylo, __shfl_xor_sync(0xffffffffu, ylo, o));
                yhi = max(yhi, __shfl_xor_sync(0xffffffffu, yhi, o));
            }
            if ((tid & 31) == 0) { s_ylo[qi] = ylo; s_yhi[qi] = yhi; }
        }
        __syncthreads();

        // ---- row-factorized gather: thread = (rowparity, h, p, xc, co).
        //      Partials for ALL 8 qi stored (disjoint), ONE sync at the end.
        {
            int rc = tid >> 7;               // row parity (warp-uniform)
            int l7 = tid & 127;
            int h = l7 >> 4, p = (l7 >> 2) & 3, xc = (l7 >> 1) & 1, co = l7 & 1;
            int up = h * 4 + p;
#pragma unroll 1
            for (int qi = 0; qi < QB; qi++) {
                int ylo = s_ylo[qi], yhi = s_yhi[qi];
                float coef = s_wx[qi][up * 2 + xc];
                int cxc = s_cx[qi][up * 2 + xc];
                const __half* base = proj + h * (HW * HD) + cxc * HD + co * 8;
                const __half* Rp = s_R + qi * RSTRIDE + up;
                __half2 a0 = __float2half2_rn(0.f);
                __half2 a1 = a0, a2 = a0, a3 = a0;
                for (int y = ylo + rc; y <= yhi; y += 2) {
                    float rw = coef * __half2float(Rp[y * 32]);
                    uint4 v = *(const uint4*)(base + y * (WSP * HD));
                    __half2 w = __float2half2_rn(rw);
                    a0 = __hfma2(*(__half2*)&v.x, w, a0);
                    a1 = __hfma2(*(__half2*)&v.y, w, a1);
                    a2 = __hfma2(*(__half2*)&v.z, w, a2);
                    a3 = __hfma2(*(__half2*)&v.w, w, a3);
                }
                // reduce over xc (xor2) and p (xor4, xor8)
                unsigned t;
#pragma unroll
                for (int o = 2; o <= 8; o <<= 1) {
                    t = __shfl_xor_sync(0xffffffffu, *(unsigned*)&a0, o);
                    a0 = __hadd2(a0, *(__half2*)&t);
                    t = __shfl_xor_sync(0xffffffffu, *(unsigned*)&a1, o);
                    a1 = __hadd2(a1, *(__half2*)&t);
                    t = __shfl_xor_sync(0xffffffffu, *(unsigned*)&a2, o);
                    a2 = __hadd2(a2, *(__half2*)&t);
                    t = __shfl_xor_sync(0xffffffffu, *(unsigned*)&a3, o);
                    a3 = __hadd2(a3, *(__half2*)&t);
                }
                if ((tid & 14) == 0) {       // lanes 0,1,16,17 of each warp
                    int lane = tid & 31;
                    int hh = ((tid >> 5) & 3) * 2 + (lane >> 4);
                    int coo = lane & 1;
                    __half2* dst = &s_pavg[qi][rc][hh * 8 + coo * 4];
                    dst[0] = a0; dst[1] = a1; dst[2] = a2; dst[3] = a3;
                }
            }
            __syncthreads();
            // combined reduce for all 8 qi: 512 half2 entries, 2 per thread
#pragma unroll
            for (int ii = 0; ii < 2; ii++) {
                int i = tid + ii * 256;
                int qi = i >> 6, e = i & 63;
                __half2 s = __hadd2(s_pavg[qi][0][e], s_pavg[qi][1][e]);
                float2 f = __half22float2(s);
                int hh = e >> 3, rem = e & 7;
                int coo = rem >> 2, k = rem & 3;
                int ch = hh * 16 + coo * 8 + k * 2;
                s_avg[qi][ch] = f.x;
                s_avg[qi][ch + 1] = f.y;
            }
            __syncthreads();
        }

        // ---- final GEMV for ALL 8 queries, one W_out read (k-split).
        //      s_part aliases the R buffer (R is rebuilt next batch).
        {
            int ch = tid & 127, half_ = tid >> 7;
            int k0 = half_ * 64;
            float a[QB];
#pragma unroll
            for (int qi = 0; qi < QB; qi++) a[qi] = 0.f;
#pragma unroll 4
            for (int k = 0; k < 64; k++) {
                float w = W_out[(k0 + k) * D + ch];
#pragma unroll
                for (int qi = 0; qi < QB; qi++)
                    a[qi] = fmaf(s_avg[qi][k0 + k], w, a[qi]);
            }
            if (half_) {
#pragma unroll
                for (int qi = 0; qi < QB; qi++)
                    s_part[qi * D + ch] = a[qi];
            }
            __syncthreads();
            if (!half_) {
                float b = b_out[ch];
#pragma unroll
                for (int qi = 0; qi < QB; qi++)
                    out[(q0 + qi) * D + ch] =
                        a[qi] + s_part[qi * D + ch] + b + 2.0f * s_q[qi][ch];
            }
        }
    }
}

// ---------------------------------------------------------------------------
extern "C" void kernel_launch(void* const* d_in, const int* in_sizes, int n_in,
                              void* d_out, int out_size) {
    const float* query  = (const float*)d_in[0];
    const float* value  = (const float*)d_in[1];
    const float* refp   = (const float*)d_in[2];
    const float* W_off  = (const float*)d_in[3];
    const float* b_off  = (const float*)d_in[4];
    const float* W_attn = (const float*)d_in[5];
    const float* b_attn = (const float*)d_in[6];
    const float* W_val  = (const float*)d_in[7];
    const float* b_val  = (const float*)d_in[8];
    const float* W_out  = (const float*)d_in[9];
    const float* b_out  = (const float*)d_in[10];
    const float* W_proj = (const float*)d_in[11];
    // b_proj (d_in[12]) unused: constant shift is softmax/argmax-invariant.

    float* out = (float*)d_out;

    int n_idx = out_size - NQ * D;
    if (n_idx < 0) n_idx = 0;
    if (n_idx > NQ) n_idx = NQ;

    int tail_n = out_size - (NQ * D + NQ);
    float* tailp = out + NQ * D + NQ;
    if (tail_n < 0) { tail_n = 0; tailp = out; }

    size_t dynR = (size_t)QB * RSTRIDE * sizeof(__half);     // 26.6 KB
    size_t dynG = (size_t)4 * GCSTRIDE * sizeof(float);      // 27.1 KB
    size_t dyn = dynR > dynG ? dynR : dynG;
    cudaFuncSetAttribute(fused_kernel,
                         cudaFuncAttributeMaxDynamicSharedMemorySize, (int)dyn);

    fused_kernel<<<GRID, TPB, dyn>>>(query, value, refp, W_off, b_off,
                                     W_attn, b_attn, W_val, b_val,
                                     W_out, b_out, W_proj,
                                     out, out + NQ * D, n_idx, tailp, tail_n);
}